// round 9
// baseline (speedup 1.0000x reference)
#include <cuda_runtime.h>

// NSE_layer: fused NSE residual + BC-mask outputs, 2048x2048 grid.
// Output flat concat: loss (3,3,2046,2046) | mask (1,3,2048,2048) | gbv (2,1,3,2048,2048)
// Concurrency: [flags+mask_edges -> loss_edge] || [mask_bulk] || [loss_bulk]; disjoint writes.

#define GNX 2048
#define GNY 2048
#define NNX 2046

__device__ unsigned char g_row_in[GNY];
__device__ unsigned char g_row_out[GNY];

// One block per row: computes flags AND writes the flag-dependent mask/gbv
// edge columns (X=0 by thread 0, X=2047 by thread 255) using in-register lay values.
__global__ __launch_bounds__(256)
void flags_kernel(const int* __restrict__ lay,
                  float* __restrict__ out_mask,
                  float* __restrict__ out_gbv)
{
    const size_t NP = (size_t)GNX * GNY;
    int y = blockIdx.x;
    const int4* row = (const int4*)(lay + (size_t)y * GNX);   // 512 int4
    int4 a = __ldg(row + threadIdx.x);
    int4 b = __ldg(row + threadIdx.x + 256);
    int fin  = (a.x == 1) | (a.y == 1) | (a.z == 1) | (a.w == 1)
             | (b.x == 1) | (b.y == 1) | (b.z == 1) | (b.w == 1);
    int fout = (a.x == 3) | (a.y == 3) | (a.z == 3) | (a.w == 3)
             | (b.x == 3) | (b.y == 3) | (b.z == 3) | (b.w == 3);
    fin  = __syncthreads_or(fin);
    fout = __syncthreads_or(fout);

    if (threadIdx.x == 0) {
        g_row_in[y]  = (unsigned char)(fin  ? 1 : 0);
        g_row_out[y] = (unsigned char)(fout ? 1 : 0);
        int L = a.x;
        float base = (L == 2) ? 0.f : 1.f;
        float gb0 = fin ? 0.f : base;
        float gb1 = fin ? 0.f : base;
        float gb2 = base;
        float gv0 = fin ? 3.f : 0.f;
        float keep = (L > 3) ? 0.f : 1.f;
        float code = (L > 3) ? (float)L : 0.f;
        size_t idx = (size_t)y * GNX;
        out_mask[0 * NP + idx] = gb0 * keep + code;
        out_mask[1 * NP + idx] = gb1 * keep + code;
        out_mask[2 * NP + idx] = gb2 * keep + code;
        out_gbv[0 * NP + idx] = gb0;
        out_gbv[1 * NP + idx] = gb1;
        out_gbv[2 * NP + idx] = gb2;
        out_gbv[3 * NP + idx] = gv0;
    }
    if (threadIdx.x == 255) {
        int L = b.w;
        float base = (L == 2) ? 0.f : 1.f;
        float gb0 = base, gb1 = base;
        float gb2 = fout ? 0.f : base;
        float keep = (L > 3) ? 0.f : 1.f;
        float code = (L > 3) ? (float)L : 0.f;
        size_t idx = (size_t)y * GNX + (GNX - 1);
        out_mask[0 * NP + idx] = gb0 * keep + code;
        out_mask[1 * NP + idx] = gb1 * keep + code;
        out_mask[2 * NP + idx] = gb2 * keep + code;
        out_gbv[0 * NP + idx] = gb0;
        out_gbv[1 * NP + idx] = gb1;
        out_gbv[2 * NP + idx] = gb2;
        out_gbv[3 * NP + idx] = 0.f;
    }
}

// ---------------- mask_bulk: flag-free; skips X=0/2047 on flag-dependent planes ----------------
__device__ __forceinline__ void store_plane_skip(float* __restrict__ base, size_t idx,
                                                 float4 val, int k)
{
    if (k == 0) {
        __stcs(base + idx + 1, val.y);
        __stcs((float2*)(base + idx + 2), make_float2(val.z, val.w));
    } else if (k == 511) {
        __stcs((float2*)(base + idx), make_float2(val.x, val.y));
        __stcs(base + idx + 2, val.z);
    } else {
        __stcs((float4*)(base + idx), val);
    }
}

__global__ __launch_bounds__(256)
void mask_bulk_kernel(const int* __restrict__ lay,
                      float* __restrict__ out_mask,
                      float* __restrict__ out_gbv)
{
    const size_t NP = (size_t)GNX * GNY;
    int k = blockIdx.x * 32 + threadIdx.x;      // 0..511
    int Y = blockIdx.y * 8  + threadIdx.y;      // 0..2047
    size_t idx = (size_t)Y * GNX + 4 * k;

    int4 L4 = __ldg((const int4*)(lay + idx));
    int Ls[4] = {L4.x, L4.y, L4.z, L4.w};

    float mk[4], gb[4];
    #pragma unroll
    for (int j = 0; j < 4; j++) {
        int L = Ls[j];
        float base = (L == 2) ? 0.f : 1.f;
        float keep = (L > 3) ? 0.f : 1.f;
        float code = (L > 3) ? (float)L : 0.f;
        gb[j] = base;
        mk[j] = base * keep + code;
    }
    float4 mkv = make_float4(mk[0], mk[1], mk[2], mk[3]);
    float4 gbv = make_float4(gb[0], gb[1], gb[2], gb[3]);
    float4 z   = make_float4(0.f, 0.f, 0.f, 0.f);

    store_plane_skip(out_mask + 0 * NP, idx, mkv, k);
    store_plane_skip(out_mask + 1 * NP, idx, mkv, k);
    store_plane_skip(out_mask + 2 * NP, idx, mkv, k);
    store_plane_skip(out_gbv + 0 * NP, idx, gbv, k);
    store_plane_skip(out_gbv + 1 * NP, idx, gbv, k);
    store_plane_skip(out_gbv + 2 * NP, idx, gbv, k);
    store_plane_skip(out_gbv + 3 * NP, idx, z,   k);
    __stcs((float4*)(out_gbv + 4 * NP + idx), z);
    __stcs((float4*)(out_gbv + 5 * NP + idx), z);
}

// ---------------- loss_bulk: flag-free, skips pixels X=1 and X=2046 ----------------
__device__ __forceinline__ void load_uvp_row_nf(
    const float* __restrict__ f0, const float* __restrict__ f1,
    const float* __restrict__ f2, const int* __restrict__ lay,
    int r, int xv, bool tail,
    float* u, float* v, float* p, int* lf_out)
{
    size_t off = (size_t)r * GNX + xv;
    float4 ua = __ldg((const float4*)(f0 + off));
    float4 va = __ldg((const float4*)(f1 + off));
    float4 pa = __ldg((const float4*)(f2 + off));
    int4   la = __ldg((const int4*)(lay + off));
    float u4 = 0.f, u5 = 0.f, v4 = 0.f, v5 = 0.f, p4 = 0.f, p5 = 0.f;
    int   l4 = 0, l5 = 0;
    if (!tail) {
        float4 ub = __ldg((const float4*)(f0 + off + 4));
        float4 vb = __ldg((const float4*)(f1 + off + 4));
        float4 pb = __ldg((const float4*)(f2 + off + 4));
        int4   lb = __ldg((const int4*)(lay + off + 4));
        u4 = ub.x; u5 = ub.y; v4 = vb.x; v5 = vb.y; p4 = pb.x; p5 = pb.y;
        l4 = lb.x; l5 = lb.y;
    }
    float uf[6] = {ua.x, ua.y, ua.z, ua.w, u4, u5};
    float vf[6] = {va.x, va.y, va.z, va.w, v4, v5};
    float pf[6] = {pa.x, pa.y, pa.z, pa.w, p4, p5};
    int   lf[6] = {la.x, la.y, la.z, la.w, l4, l5};
    #pragma unroll
    for (int i = 0; i < 6; i++) {
        float m = (lf[i] == 2) ? 0.f : 1.f;
        u[i] = uf[i] * m;
        v[i] = vf[i] * m;
        p[i] = pf[i] * m;
        if (lf_out) lf_out[i] = lf[i];
    }
}

__global__ __launch_bounds__(256, 6)
void loss_bulk_kernel(const int* __restrict__ lay,
                      const float* __restrict__ f0,
                      const float* __restrict__ f1,
                      const float* __restrict__ f2,
                      float* __restrict__ out_loss)
{
    const size_t NN = (size_t)NNX * NNX;
    int k = blockIdx.x * 32 + threadIdx.x;        // 0..511
    int Y = blockIdx.y * 8  + threadIdx.y + 1;    // 1..2048
    if (Y > GNY - 2) return;
    bool tail = (k == 511);
    int  xv   = 4 * k;                            // pixels X = xv+1 .. xv+4 (tail: 2045,2046)

    float un[6], vn[6], pn[6];
    float uc[6], vc[6], pc[6];
    float us[6], vs[6], ps[6];
    int   lc[6];
    load_uvp_row_nf(f0, f1, f2, lay, Y - 1, xv, tail, un, vn, pn, (int*)0);
    load_uvp_row_nf(f0, f1, f2, lay, Y,     xv, tail, uc, vc, pc, lc);
    load_uvp_row_nf(f0, f1, f2, lay, Y + 1, xv, tail, us, vs, ps, (int*)0);

    const float h     = (float)(0.1 / 2047.0);
    const float inv_h = 1.0f / h;
    const float nu_h2 = 0.05f / (h * h);

    float r0[4], r1[4], r2[4];
    #pragma unroll
    for (int j = 0; j < 4; j++) {
        int   L   = lc[j + 1];
        float Uc  = uc[j + 1], Vc = vc[j + 1];
        float dxu = 0.5f * (uc[j + 2] - uc[j]);
        float dyu = 0.5f * (us[j + 1] - un[j + 1]);
        float dxv = 0.5f * (vc[j + 2] - vc[j]);
        float dyv = 0.5f * (vs[j + 1] - vn[j + 1]);
        float lapu = un[j + 1] + us[j + 1] + uc[j] + uc[j + 2] - 4.0f * Uc;
        float lapv = vn[j + 1] + vs[j + 1] + vc[j] + vc[j + 2] - 4.0f * Vc;
        float cont = dxu * inv_h + dyv * inv_h;

        bool fx  = (L == 4) | (L == 8)  | (L == 11);
        bool bx  = (L == 6) | (L == 9)  | (L == 10);
        bool fy  = (L == 7) | (L == 10) | (L == 11);
        bool by  = (L == 5) | (L == 8)  | (L == 9);
        float dpx = fx ? (pc[j + 2] - pc[j + 1]) : (bx ? (pc[j + 1] - pc[j]) : 0.5f * (pc[j + 2] - pc[j]));
        float dpy = fy ? (pn[j + 1] - pc[j + 1]) : (by ? (pc[j + 1] - ps[j + 1]) : 0.5f * (ps[j + 1] - pn[j + 1]));

        float mu = Uc * dxu * inv_h + Vc * dyu * inv_h + dpx * inv_h - lapu * nu_h2;
        float mv = Uc * dxv * inv_h + Vc * dyv * inv_h + dpy * inv_h - lapv * nu_h2;

        float m = (L == 2) ? 0.f : 1.f;
        r0[j] = m * mu; r1[j] = m * mv; r2[j] = m * cont;
    }

    size_t li = (size_t)(Y - 1) * NNX + 4 * k;    // even
    #pragma unroll
    for (int rep = 0; rep < 3; rep++) {
        float* p0 = out_loss + (size_t)(0 * 3 + rep) * NN + li;
        float* p1 = out_loss + (size_t)(1 * 3 + rep) * NN + li;
        float* p2 = out_loss + (size_t)(2 * 3 + rep) * NN + li;
        if (k == 0) {
            __stcs(p0 + 1, r0[1]); __stcs((float2*)(p0 + 2), make_float2(r0[2], r0[3]));
            __stcs(p1 + 1, r1[1]); __stcs((float2*)(p1 + 2), make_float2(r1[2], r1[3]));
            __stcs(p2 + 1, r2[1]); __stcs((float2*)(p2 + 2), make_float2(r2[2], r2[3]));
        } else if (tail) {
            __stcs(p0, r0[0]);
            __stcs(p1, r1[0]);
            __stcs(p2, r2[0]);
        } else {
            __stcs((float2*)p0, make_float2(r0[0], r0[1]));
            __stcs((float2*)(p0 + 2), make_float2(r0[2], r0[3]));
            __stcs((float2*)p1, make_float2(r1[0], r1[1]));
            __stcs((float2*)(p1 + 2), make_float2(r1[2], r1[3]));
            __stcs((float2*)p2, make_float2(r2[0], r2[1]));
            __stcs((float2*)(p2 + 2), make_float2(r2[2], r2[3]));
        }
    }
}

// ---------------- loss_edge: pixels X=1 and X=2046, rows 1..2046 (needs flags) ----------------
__global__ __launch_bounds__(256)
void loss_edge_kernel(const int* __restrict__ lay,
                      const float* __restrict__ f0,
                      const float* __restrict__ f1,
                      const float* __restrict__ f2,
                      float* __restrict__ out_loss)
{
    const size_t NN = (size_t)NNX * NNX;
    int t = blockIdx.x * blockDim.x + threadIdx.x;
    int side = t & 1;
    int Y = (t >> 1) + 1;
    if (Y > GNY - 2) return;
    int X = side ? (GNX - 2) : 1;

    float u[3][3], v[3][3], p[3][3];
    int Lc = 0;
    #pragma unroll
    for (int dy = -1; dy <= 1; dy++) {
        int yy = Y + dy;
        unsigned char rin  = g_row_in[yy];
        unsigned char rout = g_row_out[yy];
        #pragma unroll
        for (int dx = -1; dx <= 1; dx++) {
            int xx = X + dx;
            size_t o = (size_t)yy * GNX + xx;
            int L = __ldg(lay + o);
            float m = (L == 2) ? 0.f : 1.f;
            float uu = __ldg(f0 + o) * m;
            float vv = __ldg(f1 + o) * m;
            float pp = __ldg(f2 + o) * m;
            if (xx == 0 && rin)        { uu = 3.f; vv = 0.f; }
            if (xx == GNX - 1 && rout) { pp = 0.f; }
            u[dy + 1][dx + 1] = uu;
            v[dy + 1][dx + 1] = vv;
            p[dy + 1][dx + 1] = pp;
            if (dy == 0 && dx == 0) Lc = L;
        }
    }

    const float h     = (float)(0.1 / 2047.0);
    const float inv_h = 1.0f / h;
    const float nu_h2 = 0.05f / (h * h);

    float Uc = u[1][1], Vc = v[1][1];
    float dxu = 0.5f * (u[1][2] - u[1][0]);
    float dyu = 0.5f * (u[2][1] - u[0][1]);
    float dxv = 0.5f * (v[1][2] - v[1][0]);
    float dyv = 0.5f * (v[2][1] - v[0][1]);
    float lapu = u[0][1] + u[2][1] + u[1][0] + u[1][2] - 4.0f * Uc;
    float lapv = v[0][1] + v[2][1] + v[1][0] + v[1][2] - 4.0f * Vc;
    float cont = dxu * inv_h + dyv * inv_h;

    int L = Lc;
    bool fx  = (L == 4) | (L == 8)  | (L == 11);
    bool bx  = (L == 6) | (L == 9)  | (L == 10);
    bool fy  = (L == 7) | (L == 10) | (L == 11);
    bool by  = (L == 5) | (L == 8)  | (L == 9);
    float dpx = fx ? (p[1][2] - p[1][1]) : (bx ? (p[1][1] - p[1][0]) : 0.5f * (p[1][2] - p[1][0]));
    float dpy = fy ? (p[0][1] - p[1][1]) : (by ? (p[1][1] - p[2][1]) : 0.5f * (p[2][1] - p[0][1]));

    float mu = Uc * dxu * inv_h + Vc * dyu * inv_h + dpx * inv_h - lapu * nu_h2;
    float mv = Uc * dxv * inv_h + Vc * dyv * inv_h + dpy * inv_h - lapv * nu_h2;

    float m = (L == 2) ? 0.f : 1.f;
    float r0 = m * mu, r1 = m * mv, r2 = m * cont;

    size_t li = (size_t)(Y - 1) * NNX + (X - 1);
    #pragma unroll
    for (int rep = 0; rep < 3; rep++) {
        out_loss[(size_t)(0 * 3 + rep) * NN + li] = r0;
        out_loss[(size_t)(1 * 3 + rep) * NN + li] = r1;
        out_loss[(size_t)(2 * 3 + rep) * NN + li] = r2;
    }
}

extern "C" void kernel_launch(void* const* d_in, const int* in_sizes, int n_in,
                              void* d_out, int out_size) {
    const int*   layout = (const int*)d_in[0];
    const float* flow   = (const float*)d_in[1];
    const size_t NP = (size_t)GNX * GNY;
    const size_t NN = (size_t)NNX * NNX;

    const int*   lay = layout + NP;        // layout[0,1]
    const float* f0  = flow;
    const float* f1  = flow + NP;
    const float* f2  = flow + 2 * NP;

    float* out      = (float*)d_out;
    float* out_loss = out;
    float* out_mask = out_loss + 9 * NN;
    float* out_gbv  = out_mask + 3 * NP;

    static cudaStream_t s1 = 0, s2 = 0;
    static cudaEvent_t  ev_fork = 0, ev_j1 = 0, ev_j2 = 0;
    if (s1 == 0) {
        cudaStreamCreateWithFlags(&s1, cudaStreamNonBlocking);
        cudaStreamCreateWithFlags(&s2, cudaStreamNonBlocking);
        cudaEventCreateWithFlags(&ev_fork, cudaEventDisableTiming);
        cudaEventCreateWithFlags(&ev_j1, cudaEventDisableTiming);
        cudaEventCreateWithFlags(&ev_j2, cudaEventDisableTiming);
    }

    cudaEventRecord(ev_fork, 0);
    cudaStreamWaitEvent(s1, ev_fork, 0);
    cudaStreamWaitEvent(s2, ev_fork, 0);

    dim3 block(32, 8);
    // longest kernel first so it claims SMs in wave 1
    loss_bulk_kernel<<<dim3(16, 256), block>>>(lay, f0, f1, f2, out_loss);
    // chain on s1: flags (+ mask/gbv edge columns) -> loss edge pixels
    flags_kernel<<<GNY, 256, 0, s1>>>(lay, out_mask, out_gbv);
    loss_edge_kernel<<<16, 256, 0, s1>>>(lay, f0, f1, f2, out_loss);
    // mask bulk, flag-free
    mask_bulk_kernel<<<dim3(16, 256), block, 0, s2>>>(lay, out_mask, out_gbv);

    cudaEventRecord(ev_j1, s1);
    cudaEventRecord(ev_j2, s2);
    cudaStreamWaitEvent(0, ev_j1, 0);
    cudaStreamWaitEvent(0, ev_j2, 0);
}

// round 10
// speedup vs baseline: 1.0660x; 1.0660x over previous
#include <cuda_runtime.h>

// NSE_layer: fused NSE residual + BC-mask outputs, 2048x2048 grid.
// Output flat concat: loss (3,3,2046,2046) | mask (1,3,2048,2048) | gbv (2,1,3,2048,2048)
// Concurrency: [flags+mask_edges -> loss_edge] || [mask_bulk] || [loss_bulk]; disjoint writes.

#define GNX 2048
#define GNY 2048
#define NNX 2046

__device__ unsigned char g_row_in[GNY];
__device__ unsigned char g_row_out[GNY];

// One block per row: computes flags AND writes the flag-dependent mask/gbv
// edge columns (X=0 by thread 0, X=2047 by thread 255) using in-register lay values.
__global__ __launch_bounds__(256)
void flags_kernel(const int* __restrict__ lay,
                  float* __restrict__ out_mask,
                  float* __restrict__ out_gbv)
{
    const size_t NP = (size_t)GNX * GNY;
    int y = blockIdx.x;
    const int4* row = (const int4*)(lay + (size_t)y * GNX);   // 512 int4
    int4 a = __ldg(row + threadIdx.x);
    int4 b = __ldg(row + threadIdx.x + 256);
    int fin  = (a.x == 1) | (a.y == 1) | (a.z == 1) | (a.w == 1)
             | (b.x == 1) | (b.y == 1) | (b.z == 1) | (b.w == 1);
    int fout = (a.x == 3) | (a.y == 3) | (a.z == 3) | (a.w == 3)
             | (b.x == 3) | (b.y == 3) | (b.z == 3) | (b.w == 3);
    fin  = __syncthreads_or(fin);
    fout = __syncthreads_or(fout);

    if (threadIdx.x == 0) {
        g_row_in[y]  = (unsigned char)(fin  ? 1 : 0);
        g_row_out[y] = (unsigned char)(fout ? 1 : 0);
        int L = a.x;
        float base = (L == 2) ? 0.f : 1.f;
        float gb0 = fin ? 0.f : base;
        float gb1 = fin ? 0.f : base;
        float gb2 = base;
        float gv0 = fin ? 3.f : 0.f;
        float keep = (L > 3) ? 0.f : 1.f;
        float code = (L > 3) ? (float)L : 0.f;
        size_t idx = (size_t)y * GNX;
        out_mask[0 * NP + idx] = gb0 * keep + code;
        out_mask[1 * NP + idx] = gb1 * keep + code;
        out_mask[2 * NP + idx] = gb2 * keep + code;
        out_gbv[0 * NP + idx] = gb0;
        out_gbv[1 * NP + idx] = gb1;
        out_gbv[2 * NP + idx] = gb2;
        out_gbv[3 * NP + idx] = gv0;
    }
    if (threadIdx.x == 255) {
        int L = b.w;
        float base = (L == 2) ? 0.f : 1.f;
        float gb0 = base, gb1 = base;
        float gb2 = fout ? 0.f : base;
        float keep = (L > 3) ? 0.f : 1.f;
        float code = (L > 3) ? (float)L : 0.f;
        size_t idx = (size_t)y * GNX + (GNX - 1);
        out_mask[0 * NP + idx] = gb0 * keep + code;
        out_mask[1 * NP + idx] = gb1 * keep + code;
        out_mask[2 * NP + idx] = gb2 * keep + code;
        out_gbv[0 * NP + idx] = gb0;
        out_gbv[1 * NP + idx] = gb1;
        out_gbv[2 * NP + idx] = gb2;
        out_gbv[3 * NP + idx] = 0.f;
    }
}

// ---------------- mask_bulk: flag-free; skips X=0/2047 on flag-dependent planes ----------------
__device__ __forceinline__ void store_plane_skip(float* __restrict__ base, size_t idx,
                                                 float4 val, int k)
{
    if (k == 0) {
        __stcs(base + idx + 1, val.y);
        __stcs((float2*)(base + idx + 2), make_float2(val.z, val.w));
    } else if (k == 511) {
        __stcs((float2*)(base + idx), make_float2(val.x, val.y));
        __stcs(base + idx + 2, val.z);
    } else {
        __stcs((float4*)(base + idx), val);
    }
}

__global__ __launch_bounds__(256)
void mask_bulk_kernel(const int* __restrict__ lay,
                      float* __restrict__ out_mask,
                      float* __restrict__ out_gbv)
{
    const size_t NP = (size_t)GNX * GNY;
    int k = blockIdx.x * 32 + threadIdx.x;      // 0..511
    int Y = blockIdx.y * 8  + threadIdx.y;      // 0..2047
    size_t idx = (size_t)Y * GNX + 4 * k;

    int4 L4 = __ldg((const int4*)(lay + idx));
    int Ls[4] = {L4.x, L4.y, L4.z, L4.w};

    float mk[4], gb[4];
    #pragma unroll
    for (int j = 0; j < 4; j++) {
        int L = Ls[j];
        float base = (L == 2) ? 0.f : 1.f;
        float keep = (L > 3) ? 0.f : 1.f;
        float code = (L > 3) ? (float)L : 0.f;
        gb[j] = base;
        mk[j] = base * keep + code;
    }
    float4 mkv = make_float4(mk[0], mk[1], mk[2], mk[3]);
    float4 gbv = make_float4(gb[0], gb[1], gb[2], gb[3]);
    float4 z   = make_float4(0.f, 0.f, 0.f, 0.f);

    store_plane_skip(out_mask + 0 * NP, idx, mkv, k);
    store_plane_skip(out_mask + 1 * NP, idx, mkv, k);
    store_plane_skip(out_mask + 2 * NP, idx, mkv, k);
    store_plane_skip(out_gbv + 0 * NP, idx, gbv, k);
    store_plane_skip(out_gbv + 1 * NP, idx, gbv, k);
    store_plane_skip(out_gbv + 2 * NP, idx, gbv, k);
    store_plane_skip(out_gbv + 3 * NP, idx, z,   k);
    __stcs((float4*)(out_gbv + 4 * NP + idx), z);
    __stcs((float4*)(out_gbv + 5 * NP + idx), z);
}

// ---------------- loss_bulk: flag-free, skips pixels X=1 and X=2046 ----------------
// Center row: full 6-wide window (positions 0..5 = x = xv..xv+5).
__device__ __forceinline__ void load_uvp_row6(
    const float* __restrict__ f0, const float* __restrict__ f1,
    const float* __restrict__ f2, const int* __restrict__ lay,
    int r, int xv, bool tail,
    float* u, float* v, float* p, int* lf_out)
{
    size_t off = (size_t)r * GNX + xv;
    float4 ua = __ldg((const float4*)(f0 + off));
    float4 va = __ldg((const float4*)(f1 + off));
    float4 pa = __ldg((const float4*)(f2 + off));
    int4   la = __ldg((const int4*)(lay + off));
    float u4 = 0.f, u5 = 0.f, v4 = 0.f, v5 = 0.f, p4 = 0.f, p5 = 0.f;
    int   l4 = 0, l5 = 0;
    if (!tail) {
        float2 ub = __ldg((const float2*)(f0 + off + 4));
        float2 vb = __ldg((const float2*)(f1 + off + 4));
        float2 pb = __ldg((const float2*)(f2 + off + 4));
        int2   lb = __ldg((const int2*)(lay + off + 4));
        u4 = ub.x; u5 = ub.y; v4 = vb.x; v5 = vb.y; p4 = pb.x; p5 = pb.y;
        l4 = lb.x; l5 = lb.y;
    }
    float uf[6] = {ua.x, ua.y, ua.z, ua.w, u4, u5};
    float vf[6] = {va.x, va.y, va.z, va.w, v4, v5};
    float pf[6] = {pa.x, pa.y, pa.z, pa.w, p4, p5};
    int   lf[6] = {la.x, la.y, la.z, la.w, l4, l5};
    #pragma unroll
    for (int i = 0; i < 6; i++) {
        float m = (lf[i] == 2) ? 0.f : 1.f;
        u[i] = uf[i] * m;
        v[i] = vf[i] * m;
        p[i] = pf[i] * m;
        lf_out[i] = lf[i];
    }
}

// Halo rows: only positions 1..4 are used by the stencil -> return 4 values per array.
__device__ __forceinline__ void load_uvp_mid4(
    const float* __restrict__ f0, const float* __restrict__ f1,
    const float* __restrict__ f2, const int* __restrict__ lay,
    int r, int xv, bool tail,
    float* u, float* v, float* p)
{
    size_t off = (size_t)r * GNX + xv;
    float4 ua = __ldg((const float4*)(f0 + off));
    float4 va = __ldg((const float4*)(f1 + off));
    float4 pa = __ldg((const float4*)(f2 + off));
    int4   la = __ldg((const int4*)(lay + off));
    float u4 = 0.f, v4 = 0.f, p4 = 0.f;
    int   l4 = 0;
    if (!tail) {
        u4 = __ldg(f0 + off + 4);
        v4 = __ldg(f1 + off + 4);
        p4 = __ldg(f2 + off + 4);
        l4 = __ldg(lay + off + 4);
    }
    float m1 = (la.y == 2) ? 0.f : 1.f;
    float m2 = (la.z == 2) ? 0.f : 1.f;
    float m3 = (la.w == 2) ? 0.f : 1.f;
    float m4 = (l4  == 2) ? 0.f : 1.f;
    u[0] = ua.y * m1; u[1] = ua.z * m2; u[2] = ua.w * m3; u[3] = u4 * m4;
    v[0] = va.y * m1; v[1] = va.z * m2; v[2] = va.w * m3; v[3] = v4 * m4;
    p[0] = pa.y * m1; p[1] = pa.z * m2; p[2] = pa.w * m3; p[3] = p4 * m4;
}

__global__ __launch_bounds__(256, 5)
void loss_bulk_kernel(const int* __restrict__ lay,
                      const float* __restrict__ f0,
                      const float* __restrict__ f1,
                      const float* __restrict__ f2,
                      float* __restrict__ out_loss)
{
    const size_t NN = (size_t)NNX * NNX;
    int k = blockIdx.x * 32 + threadIdx.x;        // 0..511
    int Y = blockIdx.y * 8  + threadIdx.y + 1;    // 1..2048
    if (Y > GNY - 2) return;
    bool tail = (k == 511);
    int  xv   = 4 * k;                            // pixels X = xv+1 .. xv+4 (tail: 2045,2046)

    float uc[6], vc[6], pc[6];
    int   lc[6];
    float un[4], vn[4], pn[4];   // row Y-1, positions 1..4
    float us[4], vs[4], ps[4];   // row Y+1, positions 1..4
    load_uvp_row6(f0, f1, f2, lay, Y, xv, tail, uc, vc, pc, lc);
    load_uvp_mid4(f0, f1, f2, lay, Y - 1, xv, tail, un, vn, pn);
    load_uvp_mid4(f0, f1, f2, lay, Y + 1, xv, tail, us, vs, ps);

    const float h     = (float)(0.1 / 2047.0);
    const float inv_h = 1.0f / h;
    const float nu_h2 = 0.05f / (h * h);

    float r0[4], r1[4], r2[4];
    #pragma unroll
    for (int j = 0; j < 4; j++) {
        int   L   = lc[j + 1];
        float Uc  = uc[j + 1], Vc = vc[j + 1];
        float dxu = 0.5f * (uc[j + 2] - uc[j]);
        float dyu = 0.5f * (us[j] - un[j]);
        float dxv = 0.5f * (vc[j + 2] - vc[j]);
        float dyv = 0.5f * (vs[j] - vn[j]);
        float lapu = un[j] + us[j] + uc[j] + uc[j + 2] - 4.0f * Uc;
        float lapv = vn[j] + vs[j] + vc[j] + vc[j + 2] - 4.0f * Vc;
        float cont = dxu * inv_h + dyv * inv_h;

        bool fx  = (L == 4) | (L == 8)  | (L == 11);
        bool bx  = (L == 6) | (L == 9)  | (L == 10);
        bool fy  = (L == 7) | (L == 10) | (L == 11);
        bool by  = (L == 5) | (L == 8)  | (L == 9);
        float dpx = fx ? (pc[j + 2] - pc[j + 1]) : (bx ? (pc[j + 1] - pc[j]) : 0.5f * (pc[j + 2] - pc[j]));
        float dpy = fy ? (pn[j] - pc[j + 1]) : (by ? (pc[j + 1] - ps[j]) : 0.5f * (ps[j] - pn[j]));

        float mu = Uc * dxu * inv_h + Vc * dyu * inv_h + dpx * inv_h - lapu * nu_h2;
        float mv = Uc * dxv * inv_h + Vc * dyv * inv_h + dpy * inv_h - lapv * nu_h2;

        float m = (L == 2) ? 0.f : 1.f;
        r0[j] = m * mu; r1[j] = m * mv; r2[j] = m * cont;
    }

    size_t li = (size_t)(Y - 1) * NNX + 4 * k;    // even
    #pragma unroll
    for (int rep = 0; rep < 3; rep++) {
        float* p0 = out_loss + (size_t)(0 * 3 + rep) * NN + li;
        float* p1 = out_loss + (size_t)(1 * 3 + rep) * NN + li;
        float* p2 = out_loss + (size_t)(2 * 3 + rep) * NN + li;
        if (k == 0) {
            __stcs(p0 + 1, r0[1]); __stcs((float2*)(p0 + 2), make_float2(r0[2], r0[3]));
            __stcs(p1 + 1, r1[1]); __stcs((float2*)(p1 + 2), make_float2(r1[2], r1[3]));
            __stcs(p2 + 1, r2[1]); __stcs((float2*)(p2 + 2), make_float2(r2[2], r2[3]));
        } else if (tail) {
            __stcs(p0, r0[0]);
            __stcs(p1, r1[0]);
            __stcs(p2, r2[0]);
        } else {
            __stcs((float2*)p0, make_float2(r0[0], r0[1]));
            __stcs((float2*)(p0 + 2), make_float2(r0[2], r0[3]));
            __stcs((float2*)p1, make_float2(r1[0], r1[1]));
            __stcs((float2*)(p1 + 2), make_float2(r1[2], r1[3]));
            __stcs((float2*)p2, make_float2(r2[0], r2[1]));
            __stcs((float2*)(p2 + 2), make_float2(r2[2], r2[3]));
        }
    }
}

// ---------------- loss_edge: pixels X=1 and X=2046, rows 1..2046 (needs flags) ----------------
__global__ __launch_bounds__(256)
void loss_edge_kernel(const int* __restrict__ lay,
                      const float* __restrict__ f0,
                      const float* __restrict__ f1,
                      const float* __restrict__ f2,
                      float* __restrict__ out_loss)
{
    const size_t NN = (size_t)NNX * NNX;
    int t = blockIdx.x * blockDim.x + threadIdx.x;
    int side = t & 1;
    int Y = (t >> 1) + 1;
    if (Y > GNY - 2) return;
    int X = side ? (GNX - 2) : 1;

    float u[3][3], v[3][3], p[3][3];
    int Lc = 0;
    #pragma unroll
    for (int dy = -1; dy <= 1; dy++) {
        int yy = Y + dy;
        unsigned char rin  = g_row_in[yy];
        unsigned char rout = g_row_out[yy];
        #pragma unroll
        for (int dx = -1; dx <= 1; dx++) {
            int xx = X + dx;
            size_t o = (size_t)yy * GNX + xx;
            int L = __ldg(lay + o);
            float m = (L == 2) ? 0.f : 1.f;
            float uu = __ldg(f0 + o) * m;
            float vv = __ldg(f1 + o) * m;
            float pp = __ldg(f2 + o) * m;
            if (xx == 0 && rin)        { uu = 3.f; vv = 0.f; }
            if (xx == GNX - 1 && rout) { pp = 0.f; }
            u[dy + 1][dx + 1] = uu;
            v[dy + 1][dx + 1] = vv;
            p[dy + 1][dx + 1] = pp;
            if (dy == 0 && dx == 0) Lc = L;
        }
    }

    const float h     = (float)(0.1 / 2047.0);
    const float inv_h = 1.0f / h;
    const float nu_h2 = 0.05f / (h * h);

    float Uc = u[1][1], Vc = v[1][1];
    float dxu = 0.5f * (u[1][2] - u[1][0]);
    float dyu = 0.5f * (u[2][1] - u[0][1]);
    float dxv = 0.5f * (v[1][2] - v[1][0]);
    float dyv = 0.5f * (v[2][1] - v[0][1]);
    float lapu = u[0][1] + u[2][1] + u[1][0] + u[1][2] - 4.0f * Uc;
    float lapv = v[0][1] + v[2][1] + v[1][0] + v[1][2] - 4.0f * Vc;
    float cont = dxu * inv_h + dyv * inv_h;

    int L = Lc;
    bool fx  = (L == 4) | (L == 8)  | (L == 11);
    bool bx  = (L == 6) | (L == 9)  | (L == 10);
    bool fy  = (L == 7) | (L == 10) | (L == 11);
    bool by  = (L == 5) | (L == 8)  | (L == 9);
    float dpx = fx ? (p[1][2] - p[1][1]) : (bx ? (p[1][1] - p[1][0]) : 0.5f * (p[1][2] - p[1][0]));
    float dpy = fy ? (p[0][1] - p[1][1]) : (by ? (p[1][1] - p[2][1]) : 0.5f * (p[2][1] - p[0][1]));

    float mu = Uc * dxu * inv_h + Vc * dyu * inv_h + dpx * inv_h - lapu * nu_h2;
    float mv = Uc * dxv * inv_h + Vc * dyv * inv_h + dpy * inv_h - lapv * nu_h2;

    float m = (L == 2) ? 0.f : 1.f;
    float r0 = m * mu, r1 = m * mv, r2 = m * cont;

    size_t li = (size_t)(Y - 1) * NNX + (X - 1);
    #pragma unroll
    for (int rep = 0; rep < 3; rep++) {
        out_loss[(size_t)(0 * 3 + rep) * NN + li] = r0;
        out_loss[(size_t)(1 * 3 + rep) * NN + li] = r1;
        out_loss[(size_t)(2 * 3 + rep) * NN + li] = r2;
    }
}

extern "C" void kernel_launch(void* const* d_in, const int* in_sizes, int n_in,
                              void* d_out, int out_size) {
    const int*   layout = (const int*)d_in[0];
    const float* flow   = (const float*)d_in[1];
    const size_t NP = (size_t)GNX * GNY;
    const size_t NN = (size_t)NNX * NNX;

    const int*   lay = layout + NP;        // layout[0,1]
    const float* f0  = flow;
    const float* f1  = flow + NP;
    const float* f2  = flow + 2 * NP;

    float* out      = (float*)d_out;
    float* out_loss = out;
    float* out_mask = out_loss + 9 * NN;
    float* out_gbv  = out_mask + 3 * NP;

    static cudaStream_t s1 = 0, s2 = 0;
    static cudaEvent_t  ev_fork = 0, ev_j1 = 0, ev_j2 = 0;
    if (s1 == 0) {
        cudaStreamCreateWithFlags(&s1, cudaStreamNonBlocking);
        cudaStreamCreateWithFlags(&s2, cudaStreamNonBlocking);
        cudaEventCreateWithFlags(&ev_fork, cudaEventDisableTiming);
        cudaEventCreateWithFlags(&ev_j1, cudaEventDisableTiming);
        cudaEventCreateWithFlags(&ev_j2, cudaEventDisableTiming);
    }

    cudaEventRecord(ev_fork, 0);
    cudaStreamWaitEvent(s1, ev_fork, 0);
    cudaStreamWaitEvent(s2, ev_fork, 0);

    dim3 block(32, 8);
    // chain on s1: flags (+ mask/gbv edge columns) -> loss edge pixels
    flags_kernel<<<GNY, 256, 0, s1>>>(lay, out_mask, out_gbv);
    loss_edge_kernel<<<16, 256, 0, s1>>>(lay, f0, f1, f2, out_loss);
    // bulk kernels, flag-free (same launch order as R8)
    mask_bulk_kernel<<<dim3(16, 256), block, 0, s2>>>(lay, out_mask, out_gbv);
    loss_bulk_kernel<<<dim3(16, 256), block>>>(lay, f0, f1, f2, out_loss);

    cudaEventRecord(ev_j1, s1);
    cudaEventRecord(ev_j2, s2);
    cudaStreamWaitEvent(0, ev_j1, 0);
    cudaStreamWaitEvent(0, ev_j2, 0);
}

// round 11
// speedup vs baseline: 1.0848x; 1.0177x over previous
#include <cuda_runtime.h>

// NSE_layer: fused NSE residual + BC-mask outputs, 2048x2048 grid.
// Output flat concat: loss (3,3,2046,2046) | mask (1,3,2048,2048) | gbv (2,1,3,2048,2048)
// Concurrency: [memset gbv_value -> flags+mask_edges -> loss_edge] || [mask_bulk 6 planes] || [loss_bulk]

#define GNX 2048
#define GNY 2048
#define NNX 2046

__device__ unsigned char g_row_in[GNY];
__device__ unsigned char g_row_out[GNY];

// One block per row: computes flags AND writes the flag-dependent mask/gbv
// edge columns (X=0 by thread 0, X=2047 by thread 255) using in-register lay values.
// Runs AFTER the gbv_value memset so its plane-3 X=0 writes survive.
__global__ __launch_bounds__(256)
void flags_kernel(const int* __restrict__ lay,
                  float* __restrict__ out_mask,
                  float* __restrict__ out_gbv)
{
    const size_t NP = (size_t)GNX * GNY;
    int y = blockIdx.x;
    const int4* row = (const int4*)(lay + (size_t)y * GNX);   // 512 int4
    int4 a = __ldg(row + threadIdx.x);
    int4 b = __ldg(row + threadIdx.x + 256);
    int fin  = (a.x == 1) | (a.y == 1) | (a.z == 1) | (a.w == 1)
             | (b.x == 1) | (b.y == 1) | (b.z == 1) | (b.w == 1);
    int fout = (a.x == 3) | (a.y == 3) | (a.z == 3) | (a.w == 3)
             | (b.x == 3) | (b.y == 3) | (b.z == 3) | (b.w == 3);
    fin  = __syncthreads_or(fin);
    fout = __syncthreads_or(fout);

    if (threadIdx.x == 0) {
        g_row_in[y]  = (unsigned char)(fin  ? 1 : 0);
        g_row_out[y] = (unsigned char)(fout ? 1 : 0);
        int L = a.x;
        float base = (L == 2) ? 0.f : 1.f;
        float gb0 = fin ? 0.f : base;
        float gb1 = fin ? 0.f : base;
        float gb2 = base;
        float gv0 = fin ? 3.f : 0.f;
        float keep = (L > 3) ? 0.f : 1.f;
        float code = (L > 3) ? (float)L : 0.f;
        size_t idx = (size_t)y * GNX;
        out_mask[0 * NP + idx] = gb0 * keep + code;
        out_mask[1 * NP + idx] = gb1 * keep + code;
        out_mask[2 * NP + idx] = gb2 * keep + code;
        out_gbv[0 * NP + idx] = gb0;
        out_gbv[1 * NP + idx] = gb1;
        out_gbv[2 * NP + idx] = gb2;
        out_gbv[3 * NP + idx] = gv0;   // inlet value on memset-zeroed plane
    }
    if (threadIdx.x == 255) {
        int L = b.w;
        float base = (L == 2) ? 0.f : 1.f;
        float gb0 = base, gb1 = base;
        float gb2 = fout ? 0.f : base;
        float keep = (L > 3) ? 0.f : 1.f;
        float code = (L > 3) ? (float)L : 0.f;
        size_t idx = (size_t)y * GNX + (GNX - 1);
        out_mask[0 * NP + idx] = gb0 * keep + code;
        out_mask[1 * NP + idx] = gb1 * keep + code;
        out_mask[2 * NP + idx] = gb2 * keep + code;
        out_gbv[0 * NP + idx] = gb0;
        out_gbv[1 * NP + idx] = gb1;
        out_gbv[2 * NP + idx] = gb2;
    }
}

// ---------------- mask_bulk: flag-free; 6 planes (gbv planes 3..5 handled by memset) ----------------
__device__ __forceinline__ void store_plane_skip(float* __restrict__ base, size_t idx,
                                                 float4 val, int k)
{
    if (k == 0) {
        __stcs(base + idx + 1, val.y);
        __stcs((float2*)(base + idx + 2), make_float2(val.z, val.w));
    } else if (k == 511) {
        __stcs((float2*)(base + idx), make_float2(val.x, val.y));
        __stcs(base + idx + 2, val.z);
    } else {
        __stcs((float4*)(base + idx), val);
    }
}

__global__ __launch_bounds__(256)
void mask_bulk_kernel(const int* __restrict__ lay,
                      float* __restrict__ out_mask,
                      float* __restrict__ out_gbv)
{
    const size_t NP = (size_t)GNX * GNY;
    int k = blockIdx.x * 32 + threadIdx.x;      // 0..511
    int Y = blockIdx.y * 8  + threadIdx.y;      // 0..2047
    size_t idx = (size_t)Y * GNX + 4 * k;

    int4 L4 = __ldg((const int4*)(lay + idx));
    int Ls[4] = {L4.x, L4.y, L4.z, L4.w};

    float mk[4], gb[4];
    #pragma unroll
    for (int j = 0; j < 4; j++) {
        int L = Ls[j];
        float base = (L == 2) ? 0.f : 1.f;
        float keep = (L > 3) ? 0.f : 1.f;
        float code = (L > 3) ? (float)L : 0.f;
        gb[j] = base;
        mk[j] = base * keep + code;
    }
    float4 mkv = make_float4(mk[0], mk[1], mk[2], mk[3]);
    float4 gbv = make_float4(gb[0], gb[1], gb[2], gb[3]);

    store_plane_skip(out_mask + 0 * NP, idx, mkv, k);
    store_plane_skip(out_mask + 1 * NP, idx, mkv, k);
    store_plane_skip(out_mask + 2 * NP, idx, mkv, k);
    store_plane_skip(out_gbv + 0 * NP, idx, gbv, k);
    store_plane_skip(out_gbv + 1 * NP, idx, gbv, k);
    store_plane_skip(out_gbv + 2 * NP, idx, gbv, k);
}

// ---------------- loss_bulk: flag-free, skips pixels X=1 and X=2046 (R8 version) ----------------
__device__ __forceinline__ void load_uvp_row_nf(
    const float* __restrict__ f0, const float* __restrict__ f1,
    const float* __restrict__ f2, const int* __restrict__ lay,
    int r, int xv, bool tail,
    float* u, float* v, float* p, int* lf_out)
{
    size_t off = (size_t)r * GNX + xv;
    float4 ua = __ldg((const float4*)(f0 + off));
    float4 va = __ldg((const float4*)(f1 + off));
    float4 pa = __ldg((const float4*)(f2 + off));
    int4   la = __ldg((const int4*)(lay + off));
    float u4 = 0.f, u5 = 0.f, v4 = 0.f, v5 = 0.f, p4 = 0.f, p5 = 0.f;
    int   l4 = 0, l5 = 0;
    if (!tail) {
        float4 ub = __ldg((const float4*)(f0 + off + 4));
        float4 vb = __ldg((const float4*)(f1 + off + 4));
        float4 pb = __ldg((const float4*)(f2 + off + 4));
        int4   lb = __ldg((const int4*)(lay + off + 4));
        u4 = ub.x; u5 = ub.y; v4 = vb.x; v5 = vb.y; p4 = pb.x; p5 = pb.y;
        l4 = lb.x; l5 = lb.y;
    }
    float uf[6] = {ua.x, ua.y, ua.z, ua.w, u4, u5};
    float vf[6] = {va.x, va.y, va.z, va.w, v4, v5};
    float pf[6] = {pa.x, pa.y, pa.z, pa.w, p4, p5};
    int   lf[6] = {la.x, la.y, la.z, la.w, l4, l5};
    #pragma unroll
    for (int i = 0; i < 6; i++) {
        float m = (lf[i] == 2) ? 0.f : 1.f;
        u[i] = uf[i] * m;
        v[i] = vf[i] * m;
        p[i] = pf[i] * m;
        if (lf_out) lf_out[i] = lf[i];
    }
}

__global__ __launch_bounds__(256)
void loss_bulk_kernel(const int* __restrict__ lay,
                      const float* __restrict__ f0,
                      const float* __restrict__ f1,
                      const float* __restrict__ f2,
                      float* __restrict__ out_loss)
{
    const size_t NN = (size_t)NNX * NNX;
    int k = blockIdx.x * 32 + threadIdx.x;        // 0..511
    int Y = blockIdx.y * 8  + threadIdx.y + 1;    // 1..2048
    if (Y > GNY - 2) return;
    bool tail = (k == 511);
    int  xv   = 4 * k;                            // pixels X = xv+1 .. xv+4 (tail: 2045,2046)

    float un[6], vn[6], pn[6];
    float uc[6], vc[6], pc[6];
    float us[6], vs[6], ps[6];
    int   lc[6];
    load_uvp_row_nf(f0, f1, f2, lay, Y - 1, xv, tail, un, vn, pn, (int*)0);
    load_uvp_row_nf(f0, f1, f2, lay, Y,     xv, tail, uc, vc, pc, lc);
    load_uvp_row_nf(f0, f1, f2, lay, Y + 1, xv, tail, us, vs, ps, (int*)0);

    const float h     = (float)(0.1 / 2047.0);
    const float inv_h = 1.0f / h;
    const float nu_h2 = 0.05f / (h * h);

    float r0[4], r1[4], r2[4];
    #pragma unroll
    for (int j = 0; j < 4; j++) {
        int   L   = lc[j + 1];
        float Uc  = uc[j + 1], Vc = vc[j + 1];
        float dxu = 0.5f * (uc[j + 2] - uc[j]);
        float dyu = 0.5f * (us[j + 1] - un[j + 1]);
        float dxv = 0.5f * (vc[j + 2] - vc[j]);
        float dyv = 0.5f * (vs[j + 1] - vn[j + 1]);
        float lapu = un[j + 1] + us[j + 1] + uc[j] + uc[j + 2] - 4.0f * Uc;
        float lapv = vn[j + 1] + vs[j + 1] + vc[j] + vc[j + 2] - 4.0f * Vc;
        float cont = dxu * inv_h + dyv * inv_h;

        bool fx  = (L == 4) | (L == 8)  | (L == 11);
        bool bx  = (L == 6) | (L == 9)  | (L == 10);
        bool fy  = (L == 7) | (L == 10) | (L == 11);
        bool by  = (L == 5) | (L == 8)  | (L == 9);
        float dpx = fx ? (pc[j + 2] - pc[j + 1]) : (bx ? (pc[j + 1] - pc[j]) : 0.5f * (pc[j + 2] - pc[j]));
        float dpy = fy ? (pn[j + 1] - pc[j + 1]) : (by ? (pc[j + 1] - ps[j + 1]) : 0.5f * (ps[j + 1] - pn[j + 1]));

        float mu = Uc * dxu * inv_h + Vc * dyu * inv_h + dpx * inv_h - lapu * nu_h2;
        float mv = Uc * dxv * inv_h + Vc * dyv * inv_h + dpy * inv_h - lapv * nu_h2;

        float m = (L == 2) ? 0.f : 1.f;
        r0[j] = m * mu; r1[j] = m * mv; r2[j] = m * cont;
    }

    size_t li = (size_t)(Y - 1) * NNX + 4 * k;    // even
    #pragma unroll
    for (int rep = 0; rep < 3; rep++) {
        float* p0 = out_loss + (size_t)(0 * 3 + rep) * NN + li;
        float* p1 = out_loss + (size_t)(1 * 3 + rep) * NN + li;
        float* p2 = out_loss + (size_t)(2 * 3 + rep) * NN + li;
        if (k == 0) {
            __stcs(p0 + 1, r0[1]); __stcs((float2*)(p0 + 2), make_float2(r0[2], r0[3]));
            __stcs(p1 + 1, r1[1]); __stcs((float2*)(p1 + 2), make_float2(r1[2], r1[3]));
            __stcs(p2 + 1, r2[1]); __stcs((float2*)(p2 + 2), make_float2(r2[2], r2[3]));
        } else if (tail) {
            __stcs(p0, r0[0]);
            __stcs(p1, r1[0]);
            __stcs(p2, r2[0]);
        } else {
            __stcs((float2*)p0, make_float2(r0[0], r0[1]));
            __stcs((float2*)(p0 + 2), make_float2(r0[2], r0[3]));
            __stcs((float2*)p1, make_float2(r1[0], r1[1]));
            __stcs((float2*)(p1 + 2), make_float2(r1[2], r1[3]));
            __stcs((float2*)p2, make_float2(r2[0], r2[1]));
            __stcs((float2*)(p2 + 2), make_float2(r2[2], r2[3]));
        }
    }
}

// ---------------- loss_edge: pixels X=1 and X=2046, rows 1..2046 (needs flags) ----------------
__global__ __launch_bounds__(256)
void loss_edge_kernel(const int* __restrict__ lay,
                      const float* __restrict__ f0,
                      const float* __restrict__ f1,
                      const float* __restrict__ f2,
                      float* __restrict__ out_loss)
{
    const size_t NN = (size_t)NNX * NNX;
    int t = blockIdx.x * blockDim.x + threadIdx.x;
    int side = t & 1;
    int Y = (t >> 1) + 1;
    if (Y > GNY - 2) return;
    int X = side ? (GNX - 2) : 1;

    float u[3][3], v[3][3], p[3][3];
    int Lc = 0;
    #pragma unroll
    for (int dy = -1; dy <= 1; dy++) {
        int yy = Y + dy;
        unsigned char rin  = g_row_in[yy];
        unsigned char rout = g_row_out[yy];
        #pragma unroll
        for (int dx = -1; dx <= 1; dx++) {
            int xx = X + dx;
            size_t o = (size_t)yy * GNX + xx;
            int L = __ldg(lay + o);
            float m = (L == 2) ? 0.f : 1.f;
            float uu = __ldg(f0 + o) * m;
            float vv = __ldg(f1 + o) * m;
            float pp = __ldg(f2 + o) * m;
            if (xx == 0 && rin)        { uu = 3.f; vv = 0.f; }
            if (xx == GNX - 1 && rout) { pp = 0.f; }
            u[dy + 1][dx + 1] = uu;
            v[dy + 1][dx + 1] = vv;
            p[dy + 1][dx + 1] = pp;
            if (dy == 0 && dx == 0) Lc = L;
        }
    }

    const float h     = (float)(0.1 / 2047.0);
    const float inv_h = 1.0f / h;
    const float nu_h2 = 0.05f / (h * h);

    float Uc = u[1][1], Vc = v[1][1];
    float dxu = 0.5f * (u[1][2] - u[1][0]);
    float dyu = 0.5f * (u[2][1] - u[0][1]);
    float dxv = 0.5f * (v[1][2] - v[1][0]);
    float dyv = 0.5f * (v[2][1] - v[0][1]);
    float lapu = u[0][1] + u[2][1] + u[1][0] + u[1][2] - 4.0f * Uc;
    float lapv = v[0][1] + v[2][1] + v[1][0] + v[1][2] - 4.0f * Vc;
    float cont = dxu * inv_h + dyv * inv_h;

    int L = Lc;
    bool fx  = (L == 4) | (L == 8)  | (L == 11);
    bool bx  = (L == 6) | (L == 9)  | (L == 10);
    bool fy  = (L == 7) | (L == 10) | (L == 11);
    bool by  = (L == 5) | (L == 8)  | (L == 9);
    float dpx = fx ? (p[1][2] - p[1][1]) : (bx ? (p[1][1] - p[1][0]) : 0.5f * (p[1][2] - p[1][0]));
    float dpy = fy ? (p[0][1] - p[1][1]) : (by ? (p[1][1] - p[2][1]) : 0.5f * (p[2][1] - p[0][1]));

    float mu = Uc * dxu * inv_h + Vc * dyu * inv_h + dpx * inv_h - lapu * nu_h2;
    float mv = Uc * dxv * inv_h + Vc * dyv * inv_h + dpy * inv_h - lapv * nu_h2;

    float m = (L == 2) ? 0.f : 1.f;
    float r0 = m * mu, r1 = m * mv, r2 = m * cont;

    size_t li = (size_t)(Y - 1) * NNX + (X - 1);
    #pragma unroll
    for (int rep = 0; rep < 3; rep++) {
        out_loss[(size_t)(0 * 3 + rep) * NN + li] = r0;
        out_loss[(size_t)(1 * 3 + rep) * NN + li] = r1;
        out_loss[(size_t)(2 * 3 + rep) * NN + li] = r2;
    }
}

extern "C" void kernel_launch(void* const* d_in, const int* in_sizes, int n_in,
                              void* d_out, int out_size) {
    const int*   layout = (const int*)d_in[0];
    const float* flow   = (const float*)d_in[1];
    const size_t NP = (size_t)GNX * GNY;
    const size_t NN = (size_t)NNX * NNX;

    const int*   lay = layout + NP;        // layout[0,1]
    const float* f0  = flow;
    const float* f1  = flow + NP;
    const float* f2  = flow + 2 * NP;

    float* out      = (float*)d_out;
    float* out_loss = out;
    float* out_mask = out_loss + 9 * NN;
    float* out_gbv  = out_mask + 3 * NP;

    static cudaStream_t s1 = 0, s2 = 0;
    static cudaEvent_t  ev_fork = 0, ev_j1 = 0, ev_j2 = 0;
    if (s1 == 0) {
        cudaStreamCreateWithFlags(&s1, cudaStreamNonBlocking);
        cudaStreamCreateWithFlags(&s2, cudaStreamNonBlocking);
        cudaEventCreateWithFlags(&ev_fork, cudaEventDisableTiming);
        cudaEventCreateWithFlags(&ev_j1, cudaEventDisableTiming);
        cudaEventCreateWithFlags(&ev_j2, cudaEventDisableTiming);
    }

    cudaEventRecord(ev_fork, 0);
    cudaStreamWaitEvent(s1, ev_fork, 0);
    cudaStreamWaitEvent(s2, ev_fork, 0);

    dim3 block(32, 8);
    // chain on s1: zero-fill gbv planes 3..5 (contiguous 50.3 MB), then flags
    // (overwrites plane-3 inlet column), then loss edge pixels
    cudaMemsetAsync(out_gbv + 3 * NP, 0, 3 * NP * sizeof(float), s1);
    flags_kernel<<<GNY, 256, 0, s1>>>(lay, out_mask, out_gbv);
    loss_edge_kernel<<<16, 256, 0, s1>>>(lay, f0, f1, f2, out_loss);
    // bulk kernels, flag-free
    mask_bulk_kernel<<<dim3(16, 256), block, 0, s2>>>(lay, out_mask, out_gbv);
    loss_bulk_kernel<<<dim3(16, 256), block>>>(lay, f0, f1, f2, out_loss);

    cudaEventRecord(ev_j1, s1);
    cudaEventRecord(ev_j2, s2);
    cudaStreamWaitEvent(0, ev_j1, 0);
    cudaStreamWaitEvent(0, ev_j2, 0);
}

// round 12
// speedup vs baseline: 1.0950x; 1.0093x over previous
#include <cuda_runtime.h>

// NSE_layer: fused NSE residual + BC-mask outputs, 2048x2048 grid.
// Output flat concat: loss (3,3,2046,2046) | mask (1,3,2048,2048) | gbv (2,1,3,2048,2048)
// Concurrency: [memset gbv_value -> flags+mask_edges -> loss_edge] || [mask_bulk 6 planes] || [loss_bulk]
// R12 change vs R11: plain stores instead of __stcs (test L2 write-coalescing hypothesis).

#define GNX 2048
#define GNY 2048
#define NNX 2046

__device__ unsigned char g_row_in[GNY];
__device__ unsigned char g_row_out[GNY];

// One block per row: computes flags AND writes the flag-dependent mask/gbv
// edge columns (X=0 by thread 0, X=2047 by thread 255) using in-register lay values.
// Runs AFTER the gbv_value memset so its plane-3 X=0 writes survive.
__global__ __launch_bounds__(256)
void flags_kernel(const int* __restrict__ lay,
                  float* __restrict__ out_mask,
                  float* __restrict__ out_gbv)
{
    const size_t NP = (size_t)GNX * GNY;
    int y = blockIdx.x;
    const int4* row = (const int4*)(lay + (size_t)y * GNX);   // 512 int4
    int4 a = __ldg(row + threadIdx.x);
    int4 b = __ldg(row + threadIdx.x + 256);
    int fin  = (a.x == 1) | (a.y == 1) | (a.z == 1) | (a.w == 1)
             | (b.x == 1) | (b.y == 1) | (b.z == 1) | (b.w == 1);
    int fout = (a.x == 3) | (a.y == 3) | (a.z == 3) | (a.w == 3)
             | (b.x == 3) | (b.y == 3) | (b.z == 3) | (b.w == 3);
    fin  = __syncthreads_or(fin);
    fout = __syncthreads_or(fout);

    if (threadIdx.x == 0) {
        g_row_in[y]  = (unsigned char)(fin  ? 1 : 0);
        g_row_out[y] = (unsigned char)(fout ? 1 : 0);
        int L = a.x;
        float base = (L == 2) ? 0.f : 1.f;
        float gb0 = fin ? 0.f : base;
        float gb1 = fin ? 0.f : base;
        float gb2 = base;
        float gv0 = fin ? 3.f : 0.f;
        float keep = (L > 3) ? 0.f : 1.f;
        float code = (L > 3) ? (float)L : 0.f;
        size_t idx = (size_t)y * GNX;
        out_mask[0 * NP + idx] = gb0 * keep + code;
        out_mask[1 * NP + idx] = gb1 * keep + code;
        out_mask[2 * NP + idx] = gb2 * keep + code;
        out_gbv[0 * NP + idx] = gb0;
        out_gbv[1 * NP + idx] = gb1;
        out_gbv[2 * NP + idx] = gb2;
        out_gbv[3 * NP + idx] = gv0;   // inlet value on memset-zeroed plane
    }
    if (threadIdx.x == 255) {
        int L = b.w;
        float base = (L == 2) ? 0.f : 1.f;
        float gb0 = base, gb1 = base;
        float gb2 = fout ? 0.f : base;
        float keep = (L > 3) ? 0.f : 1.f;
        float code = (L > 3) ? (float)L : 0.f;
        size_t idx = (size_t)y * GNX + (GNX - 1);
        out_mask[0 * NP + idx] = gb0 * keep + code;
        out_mask[1 * NP + idx] = gb1 * keep + code;
        out_mask[2 * NP + idx] = gb2 * keep + code;
        out_gbv[0 * NP + idx] = gb0;
        out_gbv[1 * NP + idx] = gb1;
        out_gbv[2 * NP + idx] = gb2;
    }
}

// ---------------- mask_bulk: flag-free; 6 planes (gbv planes 3..5 handled by memset) ----------------
__device__ __forceinline__ void store_plane_skip(float* __restrict__ base, size_t idx,
                                                 float4 val, int k)
{
    if (k == 0) {
        base[idx + 1] = val.y;
        *(float2*)(base + idx + 2) = make_float2(val.z, val.w);
    } else if (k == 511) {
        *(float2*)(base + idx) = make_float2(val.x, val.y);
        base[idx + 2] = val.z;
    } else {
        *(float4*)(base + idx) = val;
    }
}

__global__ __launch_bounds__(256)
void mask_bulk_kernel(const int* __restrict__ lay,
                      float* __restrict__ out_mask,
                      float* __restrict__ out_gbv)
{
    const size_t NP = (size_t)GNX * GNY;
    int k = blockIdx.x * 32 + threadIdx.x;      // 0..511
    int Y = blockIdx.y * 8  + threadIdx.y;      // 0..2047
    size_t idx = (size_t)Y * GNX + 4 * k;

    int4 L4 = __ldg((const int4*)(lay + idx));
    int Ls[4] = {L4.x, L4.y, L4.z, L4.w};

    float mk[4], gb[4];
    #pragma unroll
    for (int j = 0; j < 4; j++) {
        int L = Ls[j];
        float base = (L == 2) ? 0.f : 1.f;
        float keep = (L > 3) ? 0.f : 1.f;
        float code = (L > 3) ? (float)L : 0.f;
        gb[j] = base;
        mk[j] = base * keep + code;
    }
    float4 mkv = make_float4(mk[0], mk[1], mk[2], mk[3]);
    float4 gbv = make_float4(gb[0], gb[1], gb[2], gb[3]);

    store_plane_skip(out_mask + 0 * NP, idx, mkv, k);
    store_plane_skip(out_mask + 1 * NP, idx, mkv, k);
    store_plane_skip(out_mask + 2 * NP, idx, mkv, k);
    store_plane_skip(out_gbv + 0 * NP, idx, gbv, k);
    store_plane_skip(out_gbv + 1 * NP, idx, gbv, k);
    store_plane_skip(out_gbv + 2 * NP, idx, gbv, k);
}

// ---------------- loss_bulk: flag-free, skips pixels X=1 and X=2046 ----------------
__device__ __forceinline__ void load_uvp_row_nf(
    const float* __restrict__ f0, const float* __restrict__ f1,
    const float* __restrict__ f2, const int* __restrict__ lay,
    int r, int xv, bool tail,
    float* u, float* v, float* p, int* lf_out)
{
    size_t off = (size_t)r * GNX + xv;
    float4 ua = __ldg((const float4*)(f0 + off));
    float4 va = __ldg((const float4*)(f1 + off));
    float4 pa = __ldg((const float4*)(f2 + off));
    int4   la = __ldg((const int4*)(lay + off));
    float u4 = 0.f, u5 = 0.f, v4 = 0.f, v5 = 0.f, p4 = 0.f, p5 = 0.f;
    int   l4 = 0, l5 = 0;
    if (!tail) {
        float4 ub = __ldg((const float4*)(f0 + off + 4));
        float4 vb = __ldg((const float4*)(f1 + off + 4));
        float4 pb = __ldg((const float4*)(f2 + off + 4));
        int4   lb = __ldg((const int4*)(lay + off + 4));
        u4 = ub.x; u5 = ub.y; v4 = vb.x; v5 = vb.y; p4 = pb.x; p5 = pb.y;
        l4 = lb.x; l5 = lb.y;
    }
    float uf[6] = {ua.x, ua.y, ua.z, ua.w, u4, u5};
    float vf[6] = {va.x, va.y, va.z, va.w, v4, v5};
    float pf[6] = {pa.x, pa.y, pa.z, pa.w, p4, p5};
    int   lf[6] = {la.x, la.y, la.z, la.w, l4, l5};
    #pragma unroll
    for (int i = 0; i < 6; i++) {
        float m = (lf[i] == 2) ? 0.f : 1.f;
        u[i] = uf[i] * m;
        v[i] = vf[i] * m;
        p[i] = pf[i] * m;
        if (lf_out) lf_out[i] = lf[i];
    }
}

__global__ __launch_bounds__(256)
void loss_bulk_kernel(const int* __restrict__ lay,
                      const float* __restrict__ f0,
                      const float* __restrict__ f1,
                      const float* __restrict__ f2,
                      float* __restrict__ out_loss)
{
    const size_t NN = (size_t)NNX * NNX;
    int k = blockIdx.x * 32 + threadIdx.x;        // 0..511
    int Y = blockIdx.y * 8  + threadIdx.y + 1;    // 1..2048
    if (Y > GNY - 2) return;
    bool tail = (k == 511);
    int  xv   = 4 * k;                            // pixels X = xv+1 .. xv+4 (tail: 2045,2046)

    float un[6], vn[6], pn[6];
    float uc[6], vc[6], pc[6];
    float us[6], vs[6], ps[6];
    int   lc[6];
    load_uvp_row_nf(f0, f1, f2, lay, Y - 1, xv, tail, un, vn, pn, (int*)0);
    load_uvp_row_nf(f0, f1, f2, lay, Y,     xv, tail, uc, vc, pc, lc);
    load_uvp_row_nf(f0, f1, f2, lay, Y + 1, xv, tail, us, vs, ps, (int*)0);

    const float h     = (float)(0.1 / 2047.0);
    const float inv_h = 1.0f / h;
    const float nu_h2 = 0.05f / (h * h);

    float r0[4], r1[4], r2[4];
    #pragma unroll
    for (int j = 0; j < 4; j++) {
        int   L   = lc[j + 1];
        float Uc  = uc[j + 1], Vc = vc[j + 1];
        float dxu = 0.5f * (uc[j + 2] - uc[j]);
        float dyu = 0.5f * (us[j + 1] - un[j + 1]);
        float dxv = 0.5f * (vc[j + 2] - vc[j]);
        float dyv = 0.5f * (vs[j + 1] - vn[j + 1]);
        float lapu = un[j + 1] + us[j + 1] + uc[j] + uc[j + 2] - 4.0f * Uc;
        float lapv = vn[j + 1] + vs[j + 1] + vc[j] + vc[j + 2] - 4.0f * Vc;
        float cont = dxu * inv_h + dyv * inv_h;

        bool fx  = (L == 4) | (L == 8)  | (L == 11);
        bool bx  = (L == 6) | (L == 9)  | (L == 10);
        bool fy  = (L == 7) | (L == 10) | (L == 11);
        bool by  = (L == 5) | (L == 8)  | (L == 9);
        float dpx = fx ? (pc[j + 2] - pc[j + 1]) : (bx ? (pc[j + 1] - pc[j]) : 0.5f * (pc[j + 2] - pc[j]));
        float dpy = fy ? (pn[j + 1] - pc[j + 1]) : (by ? (pc[j + 1] - ps[j + 1]) : 0.5f * (ps[j + 1] - pn[j + 1]));

        float mu = Uc * dxu * inv_h + Vc * dyu * inv_h + dpx * inv_h - lapu * nu_h2;
        float mv = Uc * dxv * inv_h + Vc * dyv * inv_h + dpy * inv_h - lapv * nu_h2;

        float m = (L == 2) ? 0.f : 1.f;
        r0[j] = m * mu; r1[j] = m * mv; r2[j] = m * cont;
    }

    size_t li = (size_t)(Y - 1) * NNX + 4 * k;    // even
    #pragma unroll
    for (int rep = 0; rep < 3; rep++) {
        float* p0 = out_loss + (size_t)(0 * 3 + rep) * NN + li;
        float* p1 = out_loss + (size_t)(1 * 3 + rep) * NN + li;
        float* p2 = out_loss + (size_t)(2 * 3 + rep) * NN + li;
        if (k == 0) {
            p0[1] = r0[1]; *(float2*)(p0 + 2) = make_float2(r0[2], r0[3]);
            p1[1] = r1[1]; *(float2*)(p1 + 2) = make_float2(r1[2], r1[3]);
            p2[1] = r2[1]; *(float2*)(p2 + 2) = make_float2(r2[2], r2[3]);
        } else if (tail) {
            p0[0] = r0[0];
            p1[0] = r1[0];
            p2[0] = r2[0];
        } else {
            *(float2*)p0 = make_float2(r0[0], r0[1]);
            *(float2*)(p0 + 2) = make_float2(r0[2], r0[3]);
            *(float2*)p1 = make_float2(r1[0], r1[1]);
            *(float2*)(p1 + 2) = make_float2(r1[2], r1[3]);
            *(float2*)p2 = make_float2(r2[0], r2[1]);
            *(float2*)(p2 + 2) = make_float2(r2[2], r2[3]);
        }
    }
}

// ---------------- loss_edge: pixels X=1 and X=2046, rows 1..2046 (needs flags) ----------------
__global__ __launch_bounds__(256)
void loss_edge_kernel(const int* __restrict__ lay,
                      const float* __restrict__ f0,
                      const float* __restrict__ f1,
                      const float* __restrict__ f2,
                      float* __restrict__ out_loss)
{
    const size_t NN = (size_t)NNX * NNX;
    int t = blockIdx.x * blockDim.x + threadIdx.x;
    int side = t & 1;
    int Y = (t >> 1) + 1;
    if (Y > GNY - 2) return;
    int X = side ? (GNX - 2) : 1;

    float u[3][3], v[3][3], p[3][3];
    int Lc = 0;
    #pragma unroll
    for (int dy = -1; dy <= 1; dy++) {
        int yy = Y + dy;
        unsigned char rin  = g_row_in[yy];
        unsigned char rout = g_row_out[yy];
        #pragma unroll
        for (int dx = -1; dx <= 1; dx++) {
            int xx = X + dx;
            size_t o = (size_t)yy * GNX + xx;
            int L = __ldg(lay + o);
            float m = (L == 2) ? 0.f : 1.f;
            float uu = __ldg(f0 + o) * m;
            float vv = __ldg(f1 + o) * m;
            float pp = __ldg(f2 + o) * m;
            if (xx == 0 && rin)        { uu = 3.f; vv = 0.f; }
            if (xx == GNX - 1 && rout) { pp = 0.f; }
            u[dy + 1][dx + 1] = uu;
            v[dy + 1][dx + 1] = vv;
            p[dy + 1][dx + 1] = pp;
            if (dy == 0 && dx == 0) Lc = L;
        }
    }

    const float h     = (float)(0.1 / 2047.0);
    const float inv_h = 1.0f / h;
    const float nu_h2 = 0.05f / (h * h);

    float Uc = u[1][1], Vc = v[1][1];
    float dxu = 0.5f * (u[1][2] - u[1][0]);
    float dyu = 0.5f * (u[2][1] - u[0][1]);
    float dxv = 0.5f * (v[1][2] - v[1][0]);
    float dyv = 0.5f * (v[2][1] - v[0][1]);
    float lapu = u[0][1] + u[2][1] + u[1][0] + u[1][2] - 4.0f * Uc;
    float lapv = v[0][1] + v[2][1] + v[1][0] + v[1][2] - 4.0f * Vc;
    float cont = dxu * inv_h + dyv * inv_h;

    int L = Lc;
    bool fx  = (L == 4) | (L == 8)  | (L == 11);
    bool bx  = (L == 6) | (L == 9)  | (L == 10);
    bool fy  = (L == 7) | (L == 10) | (L == 11);
    bool by  = (L == 5) | (L == 8)  | (L == 9);
    float dpx = fx ? (p[1][2] - p[1][1]) : (bx ? (p[1][1] - p[1][0]) : 0.5f * (p[1][2] - p[1][0]));
    float dpy = fy ? (p[0][1] - p[1][1]) : (by ? (p[1][1] - p[2][1]) : 0.5f * (p[2][1] - p[0][1]));

    float mu = Uc * dxu * inv_h + Vc * dyu * inv_h + dpx * inv_h - lapu * nu_h2;
    float mv = Uc * dxv * inv_h + Vc * dyv * inv_h + dpy * inv_h - lapv * nu_h2;

    float m = (L == 2) ? 0.f : 1.f;
    float r0 = m * mu, r1 = m * mv, r2 = m * cont;

    size_t li = (size_t)(Y - 1) * NNX + (X - 1);
    #pragma unroll
    for (int rep = 0; rep < 3; rep++) {
        out_loss[(size_t)(0 * 3 + rep) * NN + li] = r0;
        out_loss[(size_t)(1 * 3 + rep) * NN + li] = r1;
        out_loss[(size_t)(2 * 3 + rep) * NN + li] = r2;
    }
}

extern "C" void kernel_launch(void* const* d_in, const int* in_sizes, int n_in,
                              void* d_out, int out_size) {
    const int*   layout = (const int*)d_in[0];
    const float* flow   = (const float*)d_in[1];
    const size_t NP = (size_t)GNX * GNY;
    const size_t NN = (size_t)NNX * NNX;

    const int*   lay = layout + NP;        // layout[0,1]
    const float* f0  = flow;
    const float* f1  = flow + NP;
    const float* f2  = flow + 2 * NP;

    float* out      = (float*)d_out;
    float* out_loss = out;
    float* out_mask = out_loss + 9 * NN;
    float* out_gbv  = out_mask + 3 * NP;

    static cudaStream_t s1 = 0, s2 = 0;
    static cudaEvent_t  ev_fork = 0, ev_j1 = 0, ev_j2 = 0;
    if (s1 == 0) {
        cudaStreamCreateWithFlags(&s1, cudaStreamNonBlocking);
        cudaStreamCreateWithFlags(&s2, cudaStreamNonBlocking);
        cudaEventCreateWithFlags(&ev_fork, cudaEventDisableTiming);
        cudaEventCreateWithFlags(&ev_j1, cudaEventDisableTiming);
        cudaEventCreateWithFlags(&ev_j2, cudaEventDisableTiming);
    }

    cudaEventRecord(ev_fork, 0);
    cudaStreamWaitEvent(s1, ev_fork, 0);
    cudaStreamWaitEvent(s2, ev_fork, 0);

    dim3 block(32, 8);
    // chain on s1: zero-fill gbv planes 3..5 (contiguous 50.3 MB), then flags
    // (overwrites plane-3 inlet column), then loss edge pixels
    cudaMemsetAsync(out_gbv + 3 * NP, 0, 3 * NP * sizeof(float), s1);
    flags_kernel<<<GNY, 256, 0, s1>>>(lay, out_mask, out_gbv);
    loss_edge_kernel<<<16, 256, 0, s1>>>(lay, f0, f1, f2, out_loss);
    // bulk kernels, flag-free
    mask_bulk_kernel<<<dim3(16, 256), block, 0, s2>>>(lay, out_mask, out_gbv);
    loss_bulk_kernel<<<dim3(16, 256), block>>>(lay, f0, f1, f2, out_loss);

    cudaEventRecord(ev_j1, s1);
    cudaEventRecord(ev_j2, s2);
    cudaStreamWaitEvent(0, ev_j1, 0);
    cudaStreamWaitEvent(0, ev_j2, 0);
}

// round 13
// speedup vs baseline: 1.1135x; 1.0169x over previous
#include <cuda_runtime.h>

// NSE_layer: fused NSE residual + BC-mask outputs, 2048x2048 grid.
// Output flat concat: loss (3,3,2046,2046) | mask (1,3,2048,2048) | gbv (2,1,3,2048,2048)
// Concurrency: [memset gbv_value -> flags+mask_edges -> loss_edge] || [mask_bulk 6 planes] || [loss_bulk]
// R13 change vs R12: loss_bulk uses a rolling y-window (8-row strip / thread) -> 2.4x fewer loads.

#define GNX 2048
#define GNY 2048
#define NNX 2046

__device__ unsigned char g_row_in[GNY];
__device__ unsigned char g_row_out[GNY];

// One block per row: computes flags AND writes the flag-dependent mask/gbv
// edge columns (X=0 by thread 0, X=2047 by thread 255) using in-register lay values.
__global__ __launch_bounds__(256)
void flags_kernel(const int* __restrict__ lay,
                  float* __restrict__ out_mask,
                  float* __restrict__ out_gbv)
{
    const size_t NP = (size_t)GNX * GNY;
    int y = blockIdx.x;
    const int4* row = (const int4*)(lay + (size_t)y * GNX);   // 512 int4
    int4 a = __ldg(row + threadIdx.x);
    int4 b = __ldg(row + threadIdx.x + 256);
    int fin  = (a.x == 1) | (a.y == 1) | (a.z == 1) | (a.w == 1)
             | (b.x == 1) | (b.y == 1) | (b.z == 1) | (b.w == 1);
    int fout = (a.x == 3) | (a.y == 3) | (a.z == 3) | (a.w == 3)
             | (b.x == 3) | (b.y == 3) | (b.z == 3) | (b.w == 3);
    fin  = __syncthreads_or(fin);
    fout = __syncthreads_or(fout);

    if (threadIdx.x == 0) {
        g_row_in[y]  = (unsigned char)(fin  ? 1 : 0);
        g_row_out[y] = (unsigned char)(fout ? 1 : 0);
        int L = a.x;
        float base = (L == 2) ? 0.f : 1.f;
        float gb0 = fin ? 0.f : base;
        float gb1 = fin ? 0.f : base;
        float gb2 = base;
        float gv0 = fin ? 3.f : 0.f;
        float keep = (L > 3) ? 0.f : 1.f;
        float code = (L > 3) ? (float)L : 0.f;
        size_t idx = (size_t)y * GNX;
        out_mask[0 * NP + idx] = gb0 * keep + code;
        out_mask[1 * NP + idx] = gb1 * keep + code;
        out_mask[2 * NP + idx] = gb2 * keep + code;
        out_gbv[0 * NP + idx] = gb0;
        out_gbv[1 * NP + idx] = gb1;
        out_gbv[2 * NP + idx] = gb2;
        out_gbv[3 * NP + idx] = gv0;   // inlet value on memset-zeroed plane
    }
    if (threadIdx.x == 255) {
        int L = b.w;
        float base = (L == 2) ? 0.f : 1.f;
        float gb0 = base, gb1 = base;
        float gb2 = fout ? 0.f : base;
        float keep = (L > 3) ? 0.f : 1.f;
        float code = (L > 3) ? (float)L : 0.f;
        size_t idx = (size_t)y * GNX + (GNX - 1);
        out_mask[0 * NP + idx] = gb0 * keep + code;
        out_mask[1 * NP + idx] = gb1 * keep + code;
        out_mask[2 * NP + idx] = gb2 * keep + code;
        out_gbv[0 * NP + idx] = gb0;
        out_gbv[1 * NP + idx] = gb1;
        out_gbv[2 * NP + idx] = gb2;
    }
}

// ---------------- mask_bulk: flag-free; 6 planes (gbv planes 3..5 handled by memset) ----------------
__device__ __forceinline__ void store_plane_skip(float* __restrict__ base, size_t idx,
                                                 float4 val, int k)
{
    if (k == 0) {
        base[idx + 1] = val.y;
        *(float2*)(base + idx + 2) = make_float2(val.z, val.w);
    } else if (k == 511) {
        *(float2*)(base + idx) = make_float2(val.x, val.y);
        base[idx + 2] = val.z;
    } else {
        *(float4*)(base + idx) = val;
    }
}

__global__ __launch_bounds__(256)
void mask_bulk_kernel(const int* __restrict__ lay,
                      float* __restrict__ out_mask,
                      float* __restrict__ out_gbv)
{
    const size_t NP = (size_t)GNX * GNY;
    int k = blockIdx.x * 32 + threadIdx.x;      // 0..511
    int Y = blockIdx.y * 8  + threadIdx.y;      // 0..2047
    size_t idx = (size_t)Y * GNX + 4 * k;

    int4 L4 = __ldg((const int4*)(lay + idx));
    int Ls[4] = {L4.x, L4.y, L4.z, L4.w};

    float mk[4], gb[4];
    #pragma unroll
    for (int j = 0; j < 4; j++) {
        int L = Ls[j];
        float base = (L == 2) ? 0.f : 1.f;
        float keep = (L > 3) ? 0.f : 1.f;
        float code = (L > 3) ? (float)L : 0.f;
        gb[j] = base;
        mk[j] = base * keep + code;
    }
    float4 mkv = make_float4(mk[0], mk[1], mk[2], mk[3]);
    float4 gbv = make_float4(gb[0], gb[1], gb[2], gb[3]);

    store_plane_skip(out_mask + 0 * NP, idx, mkv, k);
    store_plane_skip(out_mask + 1 * NP, idx, mkv, k);
    store_plane_skip(out_mask + 2 * NP, idx, mkv, k);
    store_plane_skip(out_gbv + 0 * NP, idx, gbv, k);
    store_plane_skip(out_gbv + 1 * NP, idx, gbv, k);
    store_plane_skip(out_gbv + 2 * NP, idx, gbv, k);
}

// ---------------- loss_bulk: rolling y-window, flag-free, skips pixels X=1 and X=2046 ----------------
__device__ __forceinline__ void load_uvp_row_nf(
    const float* __restrict__ f0, const float* __restrict__ f1,
    const float* __restrict__ f2, const int* __restrict__ lay,
    int r, int xv, bool tail,
    float* u, float* v, float* p, int* lf_out)
{
    size_t off = (size_t)r * GNX + xv;
    float4 ua = __ldg((const float4*)(f0 + off));
    float4 va = __ldg((const float4*)(f1 + off));
    float4 pa = __ldg((const float4*)(f2 + off));
    int4   la = __ldg((const int4*)(lay + off));
    float u4 = 0.f, u5 = 0.f, v4 = 0.f, v5 = 0.f, p4 = 0.f, p5 = 0.f;
    int   l4 = 0, l5 = 0;
    if (!tail) {
        float2 ub = __ldg((const float2*)(f0 + off + 4));
        float2 vb = __ldg((const float2*)(f1 + off + 4));
        float2 pb = __ldg((const float2*)(f2 + off + 4));
        int2   lb = __ldg((const int2*)(lay + off + 4));
        u4 = ub.x; u5 = ub.y; v4 = vb.x; v5 = vb.y; p4 = pb.x; p5 = pb.y;
        l4 = lb.x; l5 = lb.y;
    }
    float uf[6] = {ua.x, ua.y, ua.z, ua.w, u4, u5};
    float vf[6] = {va.x, va.y, va.z, va.w, v4, v5};
    float pf[6] = {pa.x, pa.y, pa.z, pa.w, p4, p5};
    int   lf[6] = {la.x, la.y, la.z, la.w, l4, l5};
    #pragma unroll
    for (int i = 0; i < 6; i++) {
        float m = (lf[i] == 2) ? 0.f : 1.f;
        u[i] = uf[i] * m;
        v[i] = vf[i] * m;
        p[i] = pf[i] * m;
        if (lf_out) lf_out[i] = lf[i];
    }
}

__global__ __launch_bounds__(256)
void loss_bulk_kernel(const int* __restrict__ lay,
                      const float* __restrict__ f0,
                      const float* __restrict__ f1,
                      const float* __restrict__ f2,
                      float* __restrict__ out_loss)
{
    const size_t NN = (size_t)NNX * NNX;
    int k  = blockIdx.x * 256 + threadIdx.x;      // 0..511 x-chunk
    int y0 = blockIdx.y * 8 + 1;                  // strip rows Y = y0 .. y0+7 (clamped to 2046)
    bool tail = (k == 511);
    int  xv   = 4 * k;                            // pixels X = xv+1 .. xv+4 (tail: 2045,2046)

    const float h     = (float)(0.1 / 2047.0);
    const float inv_h = 1.0f / h;
    const float nu_h2 = 0.05f / (h * h);

    float uN[6], vN[6], pN[6];   // row Y-1
    float uC[6], vC[6], pC[6];   // row Y
    float uS[6], vS[6], pS[6];   // row Y+1
    int   lcC[6], lcS[6];

    load_uvp_row_nf(f0, f1, f2, lay, y0 - 1, xv, tail, uN, vN, pN, (int*)0);
    load_uvp_row_nf(f0, f1, f2, lay, y0,     xv, tail, uC, vC, pC, lcC);

    #pragma unroll
    for (int it = 0; it < 8; it++) {
        int Y = y0 + it;
        if (Y > GNY - 2) break;
        load_uvp_row_nf(f0, f1, f2, lay, Y + 1, xv, tail, uS, vS, pS, lcS);

        float r0[4], r1[4], r2[4];
        #pragma unroll
        for (int j = 0; j < 4; j++) {
            int   L   = lcC[j + 1];
            float Uc  = uC[j + 1], Vc = vC[j + 1];
            float dxu = 0.5f * (uC[j + 2] - uC[j]);
            float dyu = 0.5f * (uS[j + 1] - uN[j + 1]);
            float dxv = 0.5f * (vC[j + 2] - vC[j]);
            float dyv = 0.5f * (vS[j + 1] - vN[j + 1]);
            float lapu = uN[j + 1] + uS[j + 1] + uC[j] + uC[j + 2] - 4.0f * Uc;
            float lapv = vN[j + 1] + vS[j + 1] + vC[j] + vC[j + 2] - 4.0f * Vc;
            float cont = dxu * inv_h + dyv * inv_h;

            bool fx  = (L == 4) | (L == 8)  | (L == 11);
            bool bx  = (L == 6) | (L == 9)  | (L == 10);
            bool fy  = (L == 7) | (L == 10) | (L == 11);
            bool by  = (L == 5) | (L == 8)  | (L == 9);
            float dpx = fx ? (pC[j + 2] - pC[j + 1]) : (bx ? (pC[j + 1] - pC[j]) : 0.5f * (pC[j + 2] - pC[j]));
            float dpy = fy ? (pN[j + 1] - pC[j + 1]) : (by ? (pC[j + 1] - pS[j + 1]) : 0.5f * (pS[j + 1] - pN[j + 1]));

            float mu = Uc * dxu * inv_h + Vc * dyu * inv_h + dpx * inv_h - lapu * nu_h2;
            float mv = Uc * dxv * inv_h + Vc * dyv * inv_h + dpy * inv_h - lapv * nu_h2;

            float m = (L == 2) ? 0.f : 1.f;
            r0[j] = m * mu; r1[j] = m * mv; r2[j] = m * cont;
        }

        size_t li = (size_t)(Y - 1) * NNX + 4 * k;    // even
        #pragma unroll
        for (int rep = 0; rep < 3; rep++) {
            float* p0 = out_loss + (size_t)(0 * 3 + rep) * NN + li;
            float* p1 = out_loss + (size_t)(1 * 3 + rep) * NN + li;
            float* p2 = out_loss + (size_t)(2 * 3 + rep) * NN + li;
            if (k == 0) {
                p0[1] = r0[1]; *(float2*)(p0 + 2) = make_float2(r0[2], r0[3]);
                p1[1] = r1[1]; *(float2*)(p1 + 2) = make_float2(r1[2], r1[3]);
                p2[1] = r2[1]; *(float2*)(p2 + 2) = make_float2(r2[2], r2[3]);
            } else if (tail) {
                p0[0] = r0[0];
                p1[0] = r1[0];
                p2[0] = r2[0];
            } else {
                *(float2*)p0 = make_float2(r0[0], r0[1]);
                *(float2*)(p0 + 2) = make_float2(r0[2], r0[3]);
                *(float2*)p1 = make_float2(r1[0], r1[1]);
                *(float2*)(p1 + 2) = make_float2(r1[2], r1[3]);
                *(float2*)p2 = make_float2(r2[0], r2[1]);
                *(float2*)(p2 + 2) = make_float2(r2[2], r2[3]);
            }
        }

        // roll the window: N <- C <- S
        #pragma unroll
        for (int i = 0; i < 6; i++) {
            uN[i] = uC[i]; vN[i] = vC[i]; pN[i] = pC[i];
            uC[i] = uS[i]; vC[i] = vS[i]; pC[i] = pS[i];
            lcC[i] = lcS[i];
        }
    }
}

// ---------------- loss_edge: pixels X=1 and X=2046, rows 1..2046 (needs flags) ----------------
__global__ __launch_bounds__(256)
void loss_edge_kernel(const int* __restrict__ lay,
                      const float* __restrict__ f0,
                      const float* __restrict__ f1,
                      const float* __restrict__ f2,
                      float* __restrict__ out_loss)
{
    const size_t NN = (size_t)NNX * NNX;
    int t = blockIdx.x * blockDim.x + threadIdx.x;
    int side = t & 1;
    int Y = (t >> 1) + 1;
    if (Y > GNY - 2) return;
    int X = side ? (GNX - 2) : 1;

    float u[3][3], v[3][3], p[3][3];
    int Lc = 0;
    #pragma unroll
    for (int dy = -1; dy <= 1; dy++) {
        int yy = Y + dy;
        unsigned char rin  = g_row_in[yy];
        unsigned char rout = g_row_out[yy];
        #pragma unroll
        for (int dx = -1; dx <= 1; dx++) {
            int xx = X + dx;
            size_t o = (size_t)yy * GNX + xx;
            int L = __ldg(lay + o);
            float m = (L == 2) ? 0.f : 1.f;
            float uu = __ldg(f0 + o) * m;
            float vv = __ldg(f1 + o) * m;
            float pp = __ldg(f2 + o) * m;
            if (xx == 0 && rin)        { uu = 3.f; vv = 0.f; }
            if (xx == GNX - 1 && rout) { pp = 0.f; }
            u[dy + 1][dx + 1] = uu;
            v[dy + 1][dx + 1] = vv;
            p[dy + 1][dx + 1] = pp;
            if (dy == 0 && dx == 0) Lc = L;
        }
    }

    const float h     = (float)(0.1 / 2047.0);
    const float inv_h = 1.0f / h;
    const float nu_h2 = 0.05f / (h * h);

    float Uc = u[1][1], Vc = v[1][1];
    float dxu = 0.5f * (u[1][2] - u[1][0]);
    float dyu = 0.5f * (u[2][1] - u[0][1]);
    float dxv = 0.5f * (v[1][2] - v[1][0]);
    float dyv = 0.5f * (v[2][1] - v[0][1]);
    float lapu = u[0][1] + u[2][1] + u[1][0] + u[1][2] - 4.0f * Uc;
    float lapv = v[0][1] + v[2][1] + v[1][0] + v[1][2] - 4.0f * Vc;
    float cont = dxu * inv_h + dyv * inv_h;

    int L = Lc;
    bool fx  = (L == 4) | (L == 8)  | (L == 11);
    bool bx  = (L == 6) | (L == 9)  | (L == 10);
    bool fy  = (L == 7) | (L == 10) | (L == 11);
    bool by  = (L == 5) | (L == 8)  | (L == 9);
    float dpx = fx ? (p[1][2] - p[1][1]) : (bx ? (p[1][1] - p[1][0]) : 0.5f * (p[1][2] - p[1][0]));
    float dpy = fy ? (p[0][1] - p[1][1]) : (by ? (p[1][1] - p[2][1]) : 0.5f * (p[2][1] - p[0][1]));

    float mu = Uc * dxu * inv_h + Vc * dyu * inv_h + dpx * inv_h - lapu * nu_h2;
    float mv = Uc * dxv * inv_h + Vc * dyv * inv_h + dpy * inv_h - lapv * nu_h2;

    float m = (L == 2) ? 0.f : 1.f;
    float r0 = m * mu, r1 = m * mv, r2 = m * cont;

    size_t li = (size_t)(Y - 1) * NNX + (X - 1);
    #pragma unroll
    for (int rep = 0; rep < 3; rep++) {
        out_loss[(size_t)(0 * 3 + rep) * NN + li] = r0;
        out_loss[(size_t)(1 * 3 + rep) * NN + li] = r1;
        out_loss[(size_t)(2 * 3 + rep) * NN + li] = r2;
    }
}

extern "C" void kernel_launch(void* const* d_in, const int* in_sizes, int n_in,
                              void* d_out, int out_size) {
    const int*   layout = (const int*)d_in[0];
    const float* flow   = (const float*)d_in[1];
    const size_t NP = (size_t)GNX * GNY;
    const size_t NN = (size_t)NNX * NNX;

    const int*   lay = layout + NP;        // layout[0,1]
    const float* f0  = flow;
    const float* f1  = flow + NP;
    const float* f2  = flow + 2 * NP;

    float* out      = (float*)d_out;
    float* out_loss = out;
    float* out_mask = out_loss + 9 * NN;
    float* out_gbv  = out_mask + 3 * NP;

    static cudaStream_t s1 = 0, s2 = 0;
    static cudaEvent_t  ev_fork = 0, ev_j1 = 0, ev_j2 = 0;
    if (s1 == 0) {
        cudaStreamCreateWithFlags(&s1, cudaStreamNonBlocking);
        cudaStreamCreateWithFlags(&s2, cudaStreamNonBlocking);
        cudaEventCreateWithFlags(&ev_fork, cudaEventDisableTiming);
        cudaEventCreateWithFlags(&ev_j1, cudaEventDisableTiming);
        cudaEventCreateWithFlags(&ev_j2, cudaEventDisableTiming);
    }

    cudaEventRecord(ev_fork, 0);
    cudaStreamWaitEvent(s1, ev_fork, 0);
    cudaStreamWaitEvent(s2, ev_fork, 0);

    dim3 block(32, 8);
    // chain on s1: zero-fill gbv planes 3..5 (contiguous 50.3 MB), then flags
    // (overwrites plane-3 inlet column), then loss edge pixels
    cudaMemsetAsync(out_gbv + 3 * NP, 0, 3 * NP * sizeof(float), s1);
    flags_kernel<<<GNY, 256, 0, s1>>>(lay, out_mask, out_gbv);
    loss_edge_kernel<<<16, 256, 0, s1>>>(lay, f0, f1, f2, out_loss);
    // bulk kernels, flag-free
    mask_bulk_kernel<<<dim3(16, 256), block, 0, s2>>>(lay, out_mask, out_gbv);
    loss_bulk_kernel<<<dim3(2, 256), 256>>>(lay, f0, f1, f2, out_loss);

    cudaEventRecord(ev_j1, s1);
    cudaEventRecord(ev_j2, s2);
    cudaStreamWaitEvent(0, ev_j1, 0);
    cudaStreamWaitEvent(0, ev_j2, 0);
}

// round 14
// speedup vs baseline: 1.1190x; 1.0050x over previous
#include <cuda_runtime.h>

// NSE_layer: fused NSE residual + BC-mask outputs, 2048x2048 grid.
// Output flat concat: loss (3,3,2046,2046) | mask (1,3,2048,2048) | gbv (2,1,3,2048,2048)
// Concurrency: [memset gbv_value -> flags+mask_edges -> loss_edge] || [mask_bulk 6 planes] || [loss_bulk]
// R14 change vs R13: rolling window keeps N row 4-wide (trim dead registers; occ 20.6% -> ~30%).

#define GNX 2048
#define GNY 2048
#define NNX 2046

__device__ unsigned char g_row_in[GNY];
__device__ unsigned char g_row_out[GNY];

// One block per row: computes flags AND writes the flag-dependent mask/gbv
// edge columns (X=0 by thread 0, X=2047 by thread 255) using in-register lay values.
__global__ __launch_bounds__(256)
void flags_kernel(const int* __restrict__ lay,
                  float* __restrict__ out_mask,
                  float* __restrict__ out_gbv)
{
    const size_t NP = (size_t)GNX * GNY;
    int y = blockIdx.x;
    const int4* row = (const int4*)(lay + (size_t)y * GNX);   // 512 int4
    int4 a = __ldg(row + threadIdx.x);
    int4 b = __ldg(row + threadIdx.x + 256);
    int fin  = (a.x == 1) | (a.y == 1) | (a.z == 1) | (a.w == 1)
             | (b.x == 1) | (b.y == 1) | (b.z == 1) | (b.w == 1);
    int fout = (a.x == 3) | (a.y == 3) | (a.z == 3) | (a.w == 3)
             | (b.x == 3) | (b.y == 3) | (b.z == 3) | (b.w == 3);
    fin  = __syncthreads_or(fin);
    fout = __syncthreads_or(fout);

    if (threadIdx.x == 0) {
        g_row_in[y]  = (unsigned char)(fin  ? 1 : 0);
        g_row_out[y] = (unsigned char)(fout ? 1 : 0);
        int L = a.x;
        float base = (L == 2) ? 0.f : 1.f;
        float gb0 = fin ? 0.f : base;
        float gb1 = fin ? 0.f : base;
        float gb2 = base;
        float gv0 = fin ? 3.f : 0.f;
        float keep = (L > 3) ? 0.f : 1.f;
        float code = (L > 3) ? (float)L : 0.f;
        size_t idx = (size_t)y * GNX;
        out_mask[0 * NP + idx] = gb0 * keep + code;
        out_mask[1 * NP + idx] = gb1 * keep + code;
        out_mask[2 * NP + idx] = gb2 * keep + code;
        out_gbv[0 * NP + idx] = gb0;
        out_gbv[1 * NP + idx] = gb1;
        out_gbv[2 * NP + idx] = gb2;
        out_gbv[3 * NP + idx] = gv0;   // inlet value on memset-zeroed plane
    }
    if (threadIdx.x == 255) {
        int L = b.w;
        float base = (L == 2) ? 0.f : 1.f;
        float gb0 = base, gb1 = base;
        float gb2 = fout ? 0.f : base;
        float keep = (L > 3) ? 0.f : 1.f;
        float code = (L > 3) ? (float)L : 0.f;
        size_t idx = (size_t)y * GNX + (GNX - 1);
        out_mask[0 * NP + idx] = gb0 * keep + code;
        out_mask[1 * NP + idx] = gb1 * keep + code;
        out_mask[2 * NP + idx] = gb2 * keep + code;
        out_gbv[0 * NP + idx] = gb0;
        out_gbv[1 * NP + idx] = gb1;
        out_gbv[2 * NP + idx] = gb2;
    }
}

// ---------------- mask_bulk: flag-free; 6 planes (gbv planes 3..5 handled by memset) ----------------
__device__ __forceinline__ void store_plane_skip(float* __restrict__ base, size_t idx,
                                                 float4 val, int k)
{
    if (k == 0) {
        base[idx + 1] = val.y;
        *(float2*)(base + idx + 2) = make_float2(val.z, val.w);
    } else if (k == 511) {
        *(float2*)(base + idx) = make_float2(val.x, val.y);
        base[idx + 2] = val.z;
    } else {
        *(float4*)(base + idx) = val;
    }
}

__global__ __launch_bounds__(256)
void mask_bulk_kernel(const int* __restrict__ lay,
                      float* __restrict__ out_mask,
                      float* __restrict__ out_gbv)
{
    const size_t NP = (size_t)GNX * GNY;
    int k = blockIdx.x * 32 + threadIdx.x;      // 0..511
    int Y = blockIdx.y * 8  + threadIdx.y;      // 0..2047
    size_t idx = (size_t)Y * GNX + 4 * k;

    int4 L4 = __ldg((const int4*)(lay + idx));
    int Ls[4] = {L4.x, L4.y, L4.z, L4.w};

    float mk[4], gb[4];
    #pragma unroll
    for (int j = 0; j < 4; j++) {
        int L = Ls[j];
        float base = (L == 2) ? 0.f : 1.f;
        float keep = (L > 3) ? 0.f : 1.f;
        float code = (L > 3) ? (float)L : 0.f;
        gb[j] = base;
        mk[j] = base * keep + code;
    }
    float4 mkv = make_float4(mk[0], mk[1], mk[2], mk[3]);
    float4 gbv = make_float4(gb[0], gb[1], gb[2], gb[3]);

    store_plane_skip(out_mask + 0 * NP, idx, mkv, k);
    store_plane_skip(out_mask + 1 * NP, idx, mkv, k);
    store_plane_skip(out_mask + 2 * NP, idx, mkv, k);
    store_plane_skip(out_gbv + 0 * NP, idx, gbv, k);
    store_plane_skip(out_gbv + 1 * NP, idx, gbv, k);
    store_plane_skip(out_gbv + 2 * NP, idx, gbv, k);
}

// ---------------- loss_bulk: rolling y-window (N row 4-wide), flag-free ----------------
__device__ __forceinline__ void load_uvp_row_nf(
    const float* __restrict__ f0, const float* __restrict__ f1,
    const float* __restrict__ f2, const int* __restrict__ lay,
    int r, int xv, bool tail,
    float* u, float* v, float* p, int* lf_out)
{
    size_t off = (size_t)r * GNX + xv;
    float4 ua = __ldg((const float4*)(f0 + off));
    float4 va = __ldg((const float4*)(f1 + off));
    float4 pa = __ldg((const float4*)(f2 + off));
    int4   la = __ldg((const int4*)(lay + off));
    float u4 = 0.f, u5 = 0.f, v4 = 0.f, v5 = 0.f, p4 = 0.f, p5 = 0.f;
    int   l4 = 0, l5 = 0;
    if (!tail) {
        float2 ub = __ldg((const float2*)(f0 + off + 4));
        float2 vb = __ldg((const float2*)(f1 + off + 4));
        float2 pb = __ldg((const float2*)(f2 + off + 4));
        int2   lb = __ldg((const int2*)(lay + off + 4));
        u4 = ub.x; u5 = ub.y; v4 = vb.x; v5 = vb.y; p4 = pb.x; p5 = pb.y;
        l4 = lb.x; l5 = lb.y;
    }
    float uf[6] = {ua.x, ua.y, ua.z, ua.w, u4, u5};
    float vf[6] = {va.x, va.y, va.z, va.w, v4, v5};
    float pf[6] = {pa.x, pa.y, pa.z, pa.w, p4, p5};
    int   lf[6] = {la.x, la.y, la.z, la.w, l4, l5};
    #pragma unroll
    for (int i = 0; i < 6; i++) {
        float m = (lf[i] == 2) ? 0.f : 1.f;
        u[i] = uf[i] * m;
        v[i] = vf[i] * m;
        p[i] = pf[i] * m;
        if (lf_out) lf_out[i] = lf[i];
    }
}

__global__ __launch_bounds__(256)
void loss_bulk_kernel(const int* __restrict__ lay,
                      const float* __restrict__ f0,
                      const float* __restrict__ f1,
                      const float* __restrict__ f2,
                      float* __restrict__ out_loss)
{
    const size_t NN = (size_t)NNX * NNX;
    int k  = blockIdx.x * 256 + threadIdx.x;      // 0..511 x-chunk
    int y0 = blockIdx.y * 8 + 1;                  // strip rows Y = y0 .. y0+7 (clamped to 2046)
    bool tail = (k == 511);
    int  xv   = 4 * k;                            // pixels X = xv+1 .. xv+4 (tail: 2045,2046)

    const float h     = (float)(0.1 / 2047.0);
    const float inv_h = 1.0f / h;
    const float nu_h2 = 0.05f / (h * h);

    float uN[4], vN[4], pN[4];   // row Y-1, positions 1..4 only (x = xv+1 .. xv+4)
    float uC[6], vC[6], pC[6];   // row Y, full window
    float uS[6], vS[6], pS[6];   // row Y+1 staging (becomes next C)
    int   lcC[6], lcS[6];

    {
        float t_u[6], t_v[6], t_p[6];
        load_uvp_row_nf(f0, f1, f2, lay, y0 - 1, xv, tail, t_u, t_v, t_p, (int*)0);
        #pragma unroll
        for (int i = 0; i < 4; i++) { uN[i] = t_u[i + 1]; vN[i] = t_v[i + 1]; pN[i] = t_p[i + 1]; }
    }
    load_uvp_row_nf(f0, f1, f2, lay, y0, xv, tail, uC, vC, pC, lcC);

    #pragma unroll
    for (int it = 0; it < 8; it++) {
        int Y = y0 + it;
        if (Y > GNY - 2) break;
        load_uvp_row_nf(f0, f1, f2, lay, Y + 1, xv, tail, uS, vS, pS, lcS);

        float r0[4], r1[4], r2[4];
        #pragma unroll
        for (int j = 0; j < 4; j++) {
            int   L   = lcC[j + 1];
            float Uc  = uC[j + 1], Vc = vC[j + 1];
            float dxu = 0.5f * (uC[j + 2] - uC[j]);
            float dyu = 0.5f * (uS[j + 1] - uN[j]);
            float dxv = 0.5f * (vC[j + 2] - vC[j]);
            float dyv = 0.5f * (vS[j + 1] - vN[j]);
            float lapu = uN[j] + uS[j + 1] + uC[j] + uC[j + 2] - 4.0f * Uc;
            float lapv = vN[j] + vS[j + 1] + vC[j] + vC[j + 2] - 4.0f * Vc;
            float cont = dxu * inv_h + dyv * inv_h;

            bool fx  = (L == 4) | (L == 8)  | (L == 11);
            bool bx  = (L == 6) | (L == 9)  | (L == 10);
            bool fy  = (L == 7) | (L == 10) | (L == 11);
            bool by  = (L == 5) | (L == 8)  | (L == 9);
            float dpx = fx ? (pC[j + 2] - pC[j + 1]) : (bx ? (pC[j + 1] - pC[j]) : 0.5f * (pC[j + 2] - pC[j]));
            float dpy = fy ? (pN[j] - pC[j + 1]) : (by ? (pC[j + 1] - pS[j + 1]) : 0.5f * (pS[j + 1] - pN[j]));

            float mu = Uc * dxu * inv_h + Vc * dyu * inv_h + dpx * inv_h - lapu * nu_h2;
            float mv = Uc * dxv * inv_h + Vc * dyv * inv_h + dpy * inv_h - lapv * nu_h2;

            float m = (L == 2) ? 0.f : 1.f;
            r0[j] = m * mu; r1[j] = m * mv; r2[j] = m * cont;
        }

        size_t li = (size_t)(Y - 1) * NNX + 4 * k;    // even
        #pragma unroll
        for (int rep = 0; rep < 3; rep++) {
            float* p0 = out_loss + (size_t)(0 * 3 + rep) * NN + li;
            float* p1 = out_loss + (size_t)(1 * 3 + rep) * NN + li;
            float* p2 = out_loss + (size_t)(2 * 3 + rep) * NN + li;
            if (k == 0) {
                p0[1] = r0[1]; *(float2*)(p0 + 2) = make_float2(r0[2], r0[3]);
                p1[1] = r1[1]; *(float2*)(p1 + 2) = make_float2(r1[2], r1[3]);
                p2[1] = r2[1]; *(float2*)(p2 + 2) = make_float2(r2[2], r2[3]);
            } else if (tail) {
                p0[0] = r0[0];
                p1[0] = r1[0];
                p2[0] = r2[0];
            } else {
                *(float2*)p0 = make_float2(r0[0], r0[1]);
                *(float2*)(p0 + 2) = make_float2(r0[2], r0[3]);
                *(float2*)p1 = make_float2(r1[0], r1[1]);
                *(float2*)(p1 + 2) = make_float2(r1[2], r1[3]);
                *(float2*)p2 = make_float2(r2[0], r2[1]);
                *(float2*)(p2 + 2) = make_float2(r2[2], r2[3]);
            }
        }

        // roll: N <- mid(C), C <- S
        #pragma unroll
        for (int i = 0; i < 4; i++) {
            uN[i] = uC[i + 1]; vN[i] = vC[i + 1]; pN[i] = pC[i + 1];
        }
        #pragma unroll
        for (int i = 0; i < 6; i++) {
            uC[i] = uS[i]; vC[i] = vS[i]; pC[i] = pS[i];
            lcC[i] = lcS[i];
        }
    }
}

// ---------------- loss_edge: pixels X=1 and X=2046, rows 1..2046 (needs flags) ----------------
__global__ __launch_bounds__(256)
void loss_edge_kernel(const int* __restrict__ lay,
                      const float* __restrict__ f0,
                      const float* __restrict__ f1,
                      const float* __restrict__ f2,
                      float* __restrict__ out_loss)
{
    const size_t NN = (size_t)NNX * NNX;
    int t = blockIdx.x * blockDim.x + threadIdx.x;
    int side = t & 1;
    int Y = (t >> 1) + 1;
    if (Y > GNY - 2) return;
    int X = side ? (GNX - 2) : 1;

    float u[3][3], v[3][3], p[3][3];
    int Lc = 0;
    #pragma unroll
    for (int dy = -1; dy <= 1; dy++) {
        int yy = Y + dy;
        unsigned char rin  = g_row_in[yy];
        unsigned char rout = g_row_out[yy];
        #pragma unroll
        for (int dx = -1; dx <= 1; dx++) {
            int xx = X + dx;
            size_t o = (size_t)yy * GNX + xx;
            int L = __ldg(lay + o);
            float m = (L == 2) ? 0.f : 1.f;
            float uu = __ldg(f0 + o) * m;
            float vv = __ldg(f1 + o) * m;
            float pp = __ldg(f2 + o) * m;
            if (xx == 0 && rin)        { uu = 3.f; vv = 0.f; }
            if (xx == GNX - 1 && rout) { pp = 0.f; }
            u[dy + 1][dx + 1] = uu;
            v[dy + 1][dx + 1] = vv;
            p[dy + 1][dx + 1] = pp;
            if (dy == 0 && dx == 0) Lc = L;
        }
    }

    const float h     = (float)(0.1 / 2047.0);
    const float inv_h = 1.0f / h;
    const float nu_h2 = 0.05f / (h * h);

    float Uc = u[1][1], Vc = v[1][1];
    float dxu = 0.5f * (u[1][2] - u[1][0]);
    float dyu = 0.5f * (u[2][1] - u[0][1]);
    float dxv = 0.5f * (v[1][2] - v[1][0]);
    float dyv = 0.5f * (v[2][1] - v[0][1]);
    float lapu = u[0][1] + u[2][1] + u[1][0] + u[1][2] - 4.0f * Uc;
    float lapv = v[0][1] + v[2][1] + v[1][0] + v[1][2] - 4.0f * Vc;
    float cont = dxu * inv_h + dyv * inv_h;

    int L = Lc;
    bool fx  = (L == 4) | (L == 8)  | (L == 11);
    bool bx  = (L == 6) | (L == 9)  | (L == 10);
    bool fy  = (L == 7) | (L == 10) | (L == 11);
    bool by  = (L == 5) | (L == 8)  | (L == 9);
    float dpx = fx ? (p[1][2] - p[1][1]) : (bx ? (p[1][1] - p[1][0]) : 0.5f * (p[1][2] - p[1][0]));
    float dpy = fy ? (p[0][1] - p[1][1]) : (by ? (p[1][1] - p[2][1]) : 0.5f * (p[2][1] - p[0][1]));

    float mu = Uc * dxu * inv_h + Vc * dyu * inv_h + dpx * inv_h - lapu * nu_h2;
    float mv = Uc * dxv * inv_h + Vc * dyv * inv_h + dpy * inv_h - lapv * nu_h2;

    float m = (L == 2) ? 0.f : 1.f;
    float r0 = m * mu, r1 = m * mv, r2 = m * cont;

    size_t li = (size_t)(Y - 1) * NNX + (X - 1);
    #pragma unroll
    for (int rep = 0; rep < 3; rep++) {
        out_loss[(size_t)(0 * 3 + rep) * NN + li] = r0;
        out_loss[(size_t)(1 * 3 + rep) * NN + li] = r1;
        out_loss[(size_t)(2 * 3 + rep) * NN + li] = r2;
    }
}

extern "C" void kernel_launch(void* const* d_in, const int* in_sizes, int n_in,
                              void* d_out, int out_size) {
    const int*   layout = (const int*)d_in[0];
    const float* flow   = (const float*)d_in[1];
    const size_t NP = (size_t)GNX * GNY;
    const size_t NN = (size_t)NNX * NNX;

    const int*   lay = layout + NP;        // layout[0,1]
    const float* f0  = flow;
    const float* f1  = flow + NP;
    const float* f2  = flow + 2 * NP;

    float* out      = (float*)d_out;
    float* out_loss = out;
    float* out_mask = out_loss + 9 * NN;
    float* out_gbv  = out_mask + 3 * NP;

    static cudaStream_t s1 = 0, s2 = 0;
    static cudaEvent_t  ev_fork = 0, ev_j1 = 0, ev_j2 = 0;
    if (s1 == 0) {
        cudaStreamCreateWithFlags(&s1, cudaStreamNonBlocking);
        cudaStreamCreateWithFlags(&s2, cudaStreamNonBlocking);
        cudaEventCreateWithFlags(&ev_fork, cudaEventDisableTiming);
        cudaEventCreateWithFlags(&ev_j1, cudaEventDisableTiming);
        cudaEventCreateWithFlags(&ev_j2, cudaEventDisableTiming);
    }

    cudaEventRecord(ev_fork, 0);
    cudaStreamWaitEvent(s1, ev_fork, 0);
    cudaStreamWaitEvent(s2, ev_fork, 0);

    dim3 block(32, 8);
    // chain on s1: zero-fill gbv planes 3..5 (contiguous 50.3 MB), then flags
    // (overwrites plane-3 inlet column), then loss edge pixels
    cudaMemsetAsync(out_gbv + 3 * NP, 0, 3 * NP * sizeof(float), s1);
    flags_kernel<<<GNY, 256, 0, s1>>>(lay, out_mask, out_gbv);
    loss_edge_kernel<<<16, 256, 0, s1>>>(lay, f0, f1, f2, out_loss);
    // bulk kernels, flag-free
    mask_bulk_kernel<<<dim3(16, 256), block, 0, s2>>>(lay, out_mask, out_gbv);
    loss_bulk_kernel<<<dim3(2, 256), 256>>>(lay, f0, f1, f2, out_loss);

    cudaEventRecord(ev_j1, s1);
    cudaEventRecord(ev_j2, s2);
    cudaStreamWaitEvent(0, ev_j1, 0);
    cudaStreamWaitEvent(0, ev_j2, 0);
}